// round 5
// baseline (speedup 1.0000x reference)
#include <cuda_runtime.h>
#include <stdint.h>

#define B_   2
#define L_   2048
#define D_   1024
#define H_   16
#define N3_  3072
#define MT_  4096
#define LOG2E 1.4426950408889634f

// scratch (allocation-free rule: device globals)
__device__ float g_qkv[(size_t)MT_ * N3_];   // tf32-rounded qkv
__device__ float g_z[(size_t)MT_ * D_];      // tf32-rounded attn output
__device__ float g_xr[(size_t)MT_ * D_];     // tf32-rounded x
__device__ float g_wq[(size_t)D_ * N3_];     // tf32-rounded W_qkv
__device__ float g_wo[(size_t)D_ * D_];      // tf32-rounded W_out

__device__ __forceinline__ uint32_t tf32u(float x) {
    uint32_t u; asm("cvt.rna.tf32.f32 %0, %1;" : "=r"(u) : "f"(x));
    return u;
}
__device__ __forceinline__ float to_tf32(float x) {
    return __uint_as_float(tf32u(x));
}

__device__ __forceinline__ void mma8(float* d, const uint32_t* a, const uint32_t* b) {
    asm volatile(
        "mma.sync.aligned.m16n8k8.row.col.f32.tf32.tf32.f32 "
        "{%0,%1,%2,%3}, {%4,%5,%6,%7}, {%8,%9}, {%0,%1,%2,%3};\n"
        : "+f"(d[0]), "+f"(d[1]), "+f"(d[2]), "+f"(d[3])
        : "r"(a[0]), "r"(a[1]), "r"(a[2]), "r"(a[3]), "r"(b[0]), "r"(b[1]));
}

// cp.async helpers
__device__ __forceinline__ void cpa(void* s, const void* g) {
    uint32_t sa = (uint32_t)__cvta_generic_to_shared(s);
    asm volatile("cp.async.cg.shared.global [%0], [%1], 16;\n" :: "r"(sa), "l"(g));
}
__device__ __forceinline__ void cpcommit() { asm volatile("cp.async.commit_group;\n"); }
template<int N> __device__ __forceinline__ void cpwait() {
    asm volatile("cp.async.wait_group %0;\n" :: "n"(N));
}

// fast exp on FMA/ALU pipes. x <= 0 here.
__device__ __forceinline__ float fexp(float x) {
    x = fmaxf(x, -80.0f);
    float t = fmaf(x, LOG2E, 12582912.0f);
    float n = t - 12582912.0f;
    float f = fmaf(x, LOG2E, -n);
    float p = 1.3333558e-3f;
    p = fmaf(p, f, 9.6181291e-3f);
    p = fmaf(p, f, 5.5504109e-2f);
    p = fmaf(p, f, 2.4022651e-1f);
    p = fmaf(p, f, 6.9314718e-1f);
    p = fmaf(p, f, 1.0f);
    int ni = __float_as_int(t) - 0x4B400000;
    return __int_as_float(__float_as_int(p) + (ni << 23));
}

// ---------------------------------------------------------------------------
// tf32 pre-rounding pass (operands rounded once; mma loop stays convert-free)
// ---------------------------------------------------------------------------
__global__ void tf32_round(const float4* __restrict__ in, float4* __restrict__ out, int n4) {
    int i = blockIdx.x * 256 + threadIdx.x;
    if (i < n4) {
        float4 v = in[i];
        v.x = to_tf32(v.x); v.y = to_tf32(v.y);
        v.z = to_tf32(v.z); v.w = to_tf32(v.w);
        out[i] = v;
    }
}

// ---------------------------------------------------------------------------
// tf32 mma GEMM, 3-stage cp.async pipeline, K-chunk 32 (64 mmas / barrier).
// 128x128 tile, 8 warps 2(m)x4(n), warp tile 64x32. Operands pre-rounded.
// As[128][36], Bs[32][136] per stage -> conflict-free fragment LDS.
// ---------------------------------------------------------------------------
#define KC 32
#define A_ST 36
#define B_ST 136
#define STG_F (128 * A_ST + KC * B_ST)       // 8960 floats / stage
#define GEMM_SMEM (3 * STG_F * 4)            // 107520 bytes

template<bool BIAS, bool ROUND>
__global__ __launch_bounds__(256)
void mma_gemm(const float* __restrict__ A, const float* __restrict__ Bm,
              const float* __restrict__ bias, float* __restrict__ C,
              int M, int N, int K)
{
    extern __shared__ float sm[];
    const int tid  = threadIdx.x;
    const int w    = tid >> 5, lane = tid & 31;
    const int g    = lane >> 2, tg = lane & 3;
    const int wm   = (w >> 2) * 64;
    const int wn   = (w & 3) * 32;
    const int row0 = blockIdx.y * 128, col0 = blockIdx.x * 128;

    float acc[16][4];
    #pragma unroll
    for (int i = 0; i < 16; i++)
        #pragma unroll
        for (int j = 0; j < 4; j++) acc[i][j] = 0.f;

    const int nIter = K / KC;

    auto load_stage = [&](int it) {
        const int k0 = it * KC;
        float* as = sm + (it % 3) * STG_F;
        float* bs = as + 128 * A_ST;
        #pragma unroll
        for (int i = 0; i < 4; i++) {
            int id = tid + 256 * i;
            int r = id >> 3, c = (id & 7) * 4;           // A: 128 x 32
            cpa(&as[r * A_ST + c], &A[(size_t)(row0 + r) * K + k0 + c]);
            int rb = id >> 5, nc = (id & 31) * 4;        // B: 32 x 128
            cpa(&bs[rb * B_ST + nc], &Bm[(size_t)(k0 + rb) * N + col0 + nc]);
        }
    };

    load_stage(0); cpcommit();
    load_stage(1); cpcommit();

    for (int it = 0; it < nIter; it++) {
        cpwait<1>();
        __syncthreads();
        if (it + 2 < nIter) load_stage(it + 2);
        cpcommit();

        const float* as = sm + (it % 3) * STG_F;
        const float* bs = as + 128 * A_ST;
        #pragma unroll
        for (int k8 = 0; k8 < 4; k8++) {
            const int kk = k8 * 8;
            uint32_t a[4][4], b[4][2];
            #pragma unroll
            for (int mt = 0; mt < 4; mt++) {
                const int m = wm + mt * 16;
                a[mt][0] = __float_as_uint(as[(m + g    ) * A_ST + kk + tg]);
                a[mt][1] = __float_as_uint(as[(m + g + 8) * A_ST + kk + tg]);
                a[mt][2] = __float_as_uint(as[(m + g    ) * A_ST + kk + tg + 4]);
                a[mt][3] = __float_as_uint(as[(m + g + 8) * A_ST + kk + tg + 4]);
            }
            #pragma unroll
            for (int nt = 0; nt < 4; nt++) {
                const int n = wn + nt * 8;
                b[nt][0] = __float_as_uint(bs[(kk + tg    ) * B_ST + n + g]);
                b[nt][1] = __float_as_uint(bs[(kk + tg + 4) * B_ST + n + g]);
            }
            #pragma unroll
            for (int mt = 0; mt < 4; mt++)
                #pragma unroll
                for (int nt = 0; nt < 4; nt++)
                    mma8(acc[mt * 4 + nt], a[mt], b[nt]);
        }
    }

    #pragma unroll
    for (int mt = 0; mt < 4; mt++) {
        #pragma unroll
        for (int nt = 0; nt < 4; nt++) {
            int r = row0 + wm + mt * 16 + g;
            int c = col0 + wn + nt * 8 + 2 * tg;
            float v0 = acc[mt * 4 + nt][0], v1 = acc[mt * 4 + nt][1];
            float v2 = acc[mt * 4 + nt][2], v3 = acc[mt * 4 + nt][3];
            if (BIAS) {
                float b0 = bias[c], b1 = bias[c + 1];
                v0 += b0; v1 += b1; v2 += b0; v3 += b1;
            }
            if (ROUND) {
                v0 = to_tf32(v0); v1 = to_tf32(v1);
                v2 = to_tf32(v2); v3 = to_tf32(v3);
            }
            *(float2*)&C[(size_t)r * N + c]       = make_float2(v0, v1);
            *(float2*)&C[(size_t)(r + 8) * N + c] = make_float2(v2, v3);
        }
    }
}

// ---------------------------------------------------------------------------
// Flash attention (tf32 mma). R3 loop structure; Q fragments hoisted to regs;
// mask double-buffered in smem via cp.async one iteration ahead (mask is the
// only DRAM-resident stream — qkv fits in L2).
//   out = sum(e^{s-m}*mask*v) / (sum(e^{s-m}*mask) + eps*sum(e^{s-m}))
// Block: 128 q-rows x one (b,h); warp owns 16 q-rows (softmax warp-local).
// ---------------------------------------------------------------------------
#define QS_OFF 0                         // [128][68]
#define KS_OFF 8704                      // [64][68]
#define VS_OFF (KS_OFF + 4352)          // [64][72]
#define PS_OFF (VS_OFF + 4608)          // [128][68]
#define MS_OFF (PS_OFF + 8704)          // [2][128][68]
#define ATTN_SMEM ((MS_OFF + 2 * 8704) * 4)   // 175104 bytes

__global__ __launch_bounds__(256)
void attn_mma(const float* __restrict__ qkv, const float* __restrict__ mask,
              float* __restrict__ z)
{
    extern __shared__ float sm[];
    float* Qs = sm + QS_OFF;
    float* Ks = sm + KS_OFF;
    float* Vs = sm + VS_OFF;
    float* Ps = sm + PS_OFF;

    const int tid = threadIdx.x;
    const int w = tid >> 5, lane = tid & 31;
    const int g = lane >> 2, tg = lane & 3;
    const int m0 = w * 16;
    const int bb = blockIdx.y >> 4;
    const int h  = blockIdx.y & 15;
    const int qi0 = blockIdx.x * 128;
    const size_t tok0 = (size_t)bb * L_ + qi0;
    const int hc = h * 64;
    const int lr = tid >> 4, lc = (tid & 15) * 4;

    auto load_mask = [&](int kt) {                 // 128 x 64 tile, stage kt&1
        float* ms = sm + MS_OFF + (kt & 1) * 8704;
        const float* mg = mask + (tok0) * L_ + kt * 64;
        #pragma unroll
        for (int i = 0; i < 8; i++) {
            int r = lr + 16 * i;
            cpa(&ms[r * 68 + lc], &mg[(size_t)r * L_ + lc]);
        }
    };

    // prologue: mask(0) via cp.async; Q staged synchronously
    load_mask(0); cpcommit();
    #pragma unroll
    for (int i = 0; i < 8; i++) {
        int r = lr + 16 * i;
        float4 v = *(const float4*)&qkv[(tok0 + r) * N3_ + hc + lc];
        *(float4*)&Qs[r * 68 + lc] = v;
    }
    __syncthreads();

    // hoist Q fragments (invariant over all K tiles)
    uint32_t qa[8][4];
    #pragma unroll
    for (int k8 = 0; k8 < 8; k8++) {
        const int kk = k8 * 8;
        qa[k8][0] = __float_as_uint(Qs[(m0 + g    ) * 68 + kk + tg]);
        qa[k8][1] = __float_as_uint(Qs[(m0 + g + 8) * 68 + kk + tg]);
        qa[k8][2] = __float_as_uint(Qs[(m0 + g    ) * 68 + kk + tg + 4]);
        qa[k8][3] = __float_as_uint(Qs[(m0 + g + 8) * 68 + kk + tg + 4]);
    }

    float acc[8][4];
    #pragma unroll
    for (int i = 0; i < 8; i++)
        #pragma unroll
        for (int j = 0; j < 4; j++) acc[i][j] = 0.f;
    float mp0 = -1e30f, mp1 = -1e30f;
    float se0 = 0.f, se1 = 0.f, sq0 = 0.f, sq1 = 0.f;

    for (int kt = 0; kt < L_ / 64; kt++) {
        const size_t ktok = (size_t)bb * L_ + kt * 64;
        __syncthreads();                        // prior iter fully done
        // K/V tiles (L2-resident qkv): synchronous stage
        #pragma unroll
        for (int i = 0; i < 4; i++) {
            int r = lr + 16 * i;
            float4 kv = *(const float4*)&qkv[(ktok + r) * N3_ + 1024 + hc + lc];
            *(float4*)&Ks[r * 68 + lc] = kv;
            float4 vv = *(const float4*)&qkv[(ktok + r) * N3_ + 2048 + hc + lc];
            *(float4*)&Vs[r * 72 + lc] = vv;
        }
        // prefetch next mask tile (DRAM-resident)
        if (kt + 1 < L_ / 64) load_mask(kt + 1);
        cpcommit();
        cpwait<1>();                            // mask(kt) arrived
        __syncthreads();

        const float* Ms = sm + MS_OFF + (kt & 1) * 8704;

        // S = Q @ K^T : m16 x n64
        float s[8][4];
        #pragma unroll
        for (int nt = 0; nt < 8; nt++)
            #pragma unroll
            for (int j = 0; j < 4; j++) s[nt][j] = 0.f;
        #pragma unroll
        for (int k8 = 0; k8 < 8; k8++) {
            const int kk = k8 * 8;
            #pragma unroll
            for (int nt = 0; nt < 8; nt++) {
                uint32_t b[2];
                b[0] = __float_as_uint(Ks[(nt * 8 + g) * 68 + kk + tg]);
                b[1] = __float_as_uint(Ks[(nt * 8 + g) * 68 + kk + tg + 4]);
                mma8(s[nt], qa[k8], b);
            }
        }

        // warp-local online softmax (rows g, g+8 of this warp)
        float r0 = -1e30f, r1 = -1e30f;
        #pragma unroll
        for (int nt = 0; nt < 8; nt++) {
            s[nt][0] *= 0.125f; s[nt][1] *= 0.125f;
            s[nt][2] *= 0.125f; s[nt][3] *= 0.125f;
            r0 = fmaxf(r0, fmaxf(s[nt][0], s[nt][1]));
            r1 = fmaxf(r1, fmaxf(s[nt][2], s[nt][3]));
        }
        r0 = fmaxf(r0, __shfl_xor_sync(0xffffffffu, r0, 1));
        r0 = fmaxf(r0, __shfl_xor_sync(0xffffffffu, r0, 2));
        r1 = fmaxf(r1, __shfl_xor_sync(0xffffffffu, r1, 1));
        r1 = fmaxf(r1, __shfl_xor_sync(0xffffffffu, r1, 2));

        float mn0 = fmaxf(mp0, r0), mn1 = fmaxf(mp1, r1);
        float c0 = fexp(mp0 - mn0), c1 = fexp(mp1 - mn1);
        mp0 = mn0; mp1 = mn1;

        float pe0 = 0.f, pe1 = 0.f, pm0 = 0.f, pm1 = 0.f;
        #pragma unroll
        for (int nt = 0; nt < 8; nt++) {
            float2 mk0 = *(const float2*)&Ms[(m0 + g    ) * 68 + nt * 8 + 2 * tg];
            float2 mk1 = *(const float2*)&Ms[(m0 + g + 8) * 68 + nt * 8 + 2 * tg];
            float p00 = fexp(s[nt][0] - mn0);
            float p01 = fexp(s[nt][1] - mn0);
            float p10 = fexp(s[nt][2] - mn1);
            float p11 = fexp(s[nt][3] - mn1);
            pe0 += p00 + p01; pe1 += p10 + p11;
            float q00 = p00 * mk0.x, q01 = p01 * mk0.y;
            float q10 = p10 * mk1.x, q11 = p11 * mk1.y;
            pm0 += q00 + q01; pm1 += q10 + q11;
            *(float2*)&Ps[(m0 + g    ) * 68 + nt * 8 + 2 * tg] =
                make_float2(to_tf32(q00), to_tf32(q01));
            *(float2*)&Ps[(m0 + g + 8) * 68 + nt * 8 + 2 * tg] =
                make_float2(to_tf32(q10), to_tf32(q11));
        }
        pe0 += __shfl_xor_sync(0xffffffffu, pe0, 1);
        pe0 += __shfl_xor_sync(0xffffffffu, pe0, 2);
        pe1 += __shfl_xor_sync(0xffffffffu, pe1, 1);
        pe1 += __shfl_xor_sync(0xffffffffu, pe1, 2);
        pm0 += __shfl_xor_sync(0xffffffffu, pm0, 1);
        pm0 += __shfl_xor_sync(0xffffffffu, pm0, 2);
        pm1 += __shfl_xor_sync(0xffffffffu, pm1, 1);
        pm1 += __shfl_xor_sync(0xffffffffu, pm1, 2);
        se0 = se0 * c0 + pe0; se1 = se1 * c1 + pe1;
        sq0 = sq0 * c0 + pm0; sq1 = sq1 * c1 + pm1;
        #pragma unroll
        for (int nt = 0; nt < 8; nt++) {
            acc[nt][0] *= c0; acc[nt][1] *= c0;
            acc[nt][2] *= c1; acc[nt][3] *= c1;
        }
        __syncwarp();   // Ps rows are warp-private

        // acc += P @ V : m16 x n64(dh)
        #pragma unroll
        for (int k8 = 0; k8 < 8; k8++) {
            const int kk = k8 * 8;
            uint32_t a[4];
            a[0] = __float_as_uint(Ps[(m0 + g    ) * 68 + kk + tg]);
            a[1] = __float_as_uint(Ps[(m0 + g + 8) * 68 + kk + tg]);
            a[2] = __float_as_uint(Ps[(m0 + g    ) * 68 + kk + tg + 4]);
            a[3] = __float_as_uint(Ps[(m0 + g + 8) * 68 + kk + tg + 4]);
            #pragma unroll
            for (int nt = 0; nt < 8; nt++) {
                uint32_t b[2];
                b[0] = __float_as_uint(Vs[(kk + tg    ) * 72 + nt * 8 + g]);
                b[1] = __float_as_uint(Vs[(kk + tg + 4) * 72 + nt * 8 + g]);
                mma8(acc[nt], a, b);
            }
        }
    }

    // epilogue: renorm, tf32-round for out-proj, write z
    float inv0 = 1.0f / (sq0 + 1e-10f * se0 + 1e-30f);
    float inv1 = 1.0f / (sq1 + 1e-10f * se1 + 1e-30f);
    #pragma unroll
    for (int nt = 0; nt < 8; nt++) {
        int c = hc + nt * 8 + 2 * tg;
        *(float2*)&z[(tok0 + m0 + g) * D_ + c] =
            make_float2(to_tf32(acc[nt][0] * inv0), to_tf32(acc[nt][1] * inv0));
        *(float2*)&z[(tok0 + m0 + g + 8) * D_ + c] =
            make_float2(to_tf32(acc[nt][2] * inv1), to_tf32(acc[nt][3] * inv1));
    }
}

// ---------------------------------------------------------------------------
extern "C" void kernel_launch(void* const* d_in, const int* in_sizes, int n_in,
                              void* d_out, int out_size)
{
    const float* x    = (const float*)d_in[0];
    const float* mask = (const float*)d_in[1];
    const float* Wqkv = (const float*)d_in[2];
    const float* Wout = (const float*)d_in[3];
    const float* bout = (const float*)d_in[4];
    float* out = (float*)d_out;

    float *qkvp, *zp, *xr, *wq, *wo;
    cudaGetSymbolAddress((void**)&qkvp, g_qkv);
    cudaGetSymbolAddress((void**)&zp,   g_z);
    cudaGetSymbolAddress((void**)&xr,   g_xr);
    cudaGetSymbolAddress((void**)&wq,   g_wq);
    cudaGetSymbolAddress((void**)&wo,   g_wo);

    cudaFuncSetAttribute(mma_gemm<false, true>,
                         cudaFuncAttributeMaxDynamicSharedMemorySize, GEMM_SMEM);
    cudaFuncSetAttribute(mma_gemm<true, false>,
                         cudaFuncAttributeMaxDynamicSharedMemorySize, GEMM_SMEM);
    cudaFuncSetAttribute(attn_mma,
                         cudaFuncAttributeMaxDynamicSharedMemorySize, ATTN_SMEM);

    // 0) pre-round operands to tf32 (RNA) — keeps the mma loops convert-free
    {
        int n4x = MT_ * D_ / 4, n4q = D_ * N3_ / 4, n4o = D_ * D_ / 4;
        tf32_round<<<(n4x + 255) / 256, 256>>>((const float4*)x,    (float4*)xr, n4x);
        tf32_round<<<(n4q + 255) / 256, 256>>>((const float4*)Wqkv, (float4*)wq, n4q);
        tf32_round<<<(n4o + 255) / 256, 256>>>((const float4*)Wout, (float4*)wo, n4o);
    }

    // 1) QKV projection (epilogue rounds output for attention)
    mma_gemm<false, true><<<dim3(N3_ / 128, MT_ / 128), 256, GEMM_SMEM>>>(
        xr, wq, nullptr, qkvp, MT_, N3_, D_);

    // 2) masked flash attention (writes tf32-rounded z)
    attn_mma<<<dim3(L_ / 128, B_ * H_), 256, ATTN_SMEM>>>(qkvp, mask, zp);

    // 3) output projection + bias (exact fp32 output)
    mma_gemm<true, false><<<dim3(D_ / 128, MT_ / 128), 256, GEMM_SMEM>>>(
        zp, wo, bout, out, MT_, D_, D_);
}

// round 6
// speedup vs baseline: 1.7902x; 1.7902x over previous
#include <cuda_runtime.h>
#include <stdint.h>

#define B_   2
#define L_   2048
#define D_   1024
#define H_   16
#define N3_  3072
#define MT_  4096
#define LOG2E 1.4426950408889634f

// scratch (allocation-free rule: device globals)
__device__ float g_qkv[(size_t)MT_ * N3_];   // tf32-rounded qkv
__device__ float g_z[(size_t)MT_ * D_];      // tf32-rounded attn output
__device__ float g_xr[(size_t)MT_ * D_];     // tf32-rounded x
__device__ float g_wq[(size_t)D_ * N3_];     // tf32-rounded W_qkv
__device__ float g_wo[(size_t)D_ * D_];      // tf32-rounded W_out

__device__ __forceinline__ uint32_t tf32u(float x) {
    uint32_t u; asm("cvt.rna.tf32.f32 %0, %1;" : "=r"(u) : "f"(x));
    return u;
}
__device__ __forceinline__ float to_tf32(float x) {
    return __uint_as_float(tf32u(x));
}

__device__ __forceinline__ void mma8(float* d, const uint32_t* a, const uint32_t* b) {
    asm volatile(
        "mma.sync.aligned.m16n8k8.row.col.f32.tf32.tf32.f32 "
        "{%0,%1,%2,%3}, {%4,%5,%6,%7}, {%8,%9}, {%0,%1,%2,%3};\n"
        : "+f"(d[0]), "+f"(d[1]), "+f"(d[2]), "+f"(d[3])
        : "r"(a[0]), "r"(a[1]), "r"(a[2]), "r"(a[3]), "r"(b[0]), "r"(b[1]));
}

// cp.async helpers
__device__ __forceinline__ void cpa(void* s, const void* g) {
    uint32_t sa = (uint32_t)__cvta_generic_to_shared(s);
    asm volatile("cp.async.cg.shared.global [%0], [%1], 16;\n" :: "r"(sa), "l"(g));
}
__device__ __forceinline__ void cpcommit() { asm volatile("cp.async.commit_group;\n"); }
template<int N> __device__ __forceinline__ void cpwait() {
    asm volatile("cp.async.wait_group %0;\n" :: "n"(N));
}

// fast exp on FMA/ALU pipes. x <= 0 here.
__device__ __forceinline__ float fexp(float x) {
    x = fmaxf(x, -80.0f);
    float t = fmaf(x, LOG2E, 12582912.0f);
    float n = t - 12582912.0f;
    float f = fmaf(x, LOG2E, -n);
    float p = 1.3333558e-3f;
    p = fmaf(p, f, 9.6181291e-3f);
    p = fmaf(p, f, 5.5504109e-2f);
    p = fmaf(p, f, 2.4022651e-1f);
    p = fmaf(p, f, 6.9314718e-1f);
    p = fmaf(p, f, 1.0f);
    int ni = __float_as_int(t) - 0x4B400000;
    return __int_as_float(__float_as_int(p) + (ni << 23));
}

// ---------------------------------------------------------------------------
// tf32 pre-rounding pass (operands rounded once; mma loops stay convert-free)
// ---------------------------------------------------------------------------
__global__ void tf32_round(const float4* __restrict__ in, float4* __restrict__ out, int n4) {
    int i = blockIdx.x * 256 + threadIdx.x;
    if (i < n4) {
        float4 v = in[i];
        v.x = to_tf32(v.x); v.y = to_tf32(v.y);
        v.z = to_tf32(v.z); v.w = to_tf32(v.w);
        out[i] = v;
    }
}

// ---------------------------------------------------------------------------
// tf32 mma GEMM, 2-stage cp.async double buffer, K-chunk 32.
// 128x128 tile, 8 warps 2(m)x4(n), warp tile 64x32. Operands pre-rounded.
// Budget discipline: smem 2x35840B = 71680 (<114KB), launch_bounds(256,2)
// caps regs at 128 -> 2 CTAs/SM preserved (the R4/R5 failure mode).
// ---------------------------------------------------------------------------
#define KC 32
#define A_ST 36
#define B_ST 136
#define STG_F (128 * A_ST + KC * B_ST)       // 8960 floats / stage
#define GEMM_SMEM (2 * STG_F * 4)            // 71680 bytes

template<bool BIAS, bool ROUND>
__global__ __launch_bounds__(256, 2)
void mma_gemm(const float* __restrict__ A, const float* __restrict__ Bm,
              const float* __restrict__ bias, float* __restrict__ C,
              int M, int N, int K)
{
    extern __shared__ float sm[];
    const int tid  = threadIdx.x;
    const int w    = tid >> 5, lane = tid & 31;
    const int g    = lane >> 2, tg = lane & 3;
    const int wm   = (w >> 2) * 64;
    const int wn   = (w & 3) * 32;
    const int row0 = blockIdx.y * 128, col0 = blockIdx.x * 128;

    float acc[16][4];
    #pragma unroll
    for (int i = 0; i < 16; i++)
        #pragma unroll
        for (int j = 0; j < 4; j++) acc[i][j] = 0.f;

    const int nIter = K / KC;

    auto load_stage = [&](int it) {
        const int k0 = it * KC;
        float* as = sm + (it & 1) * STG_F;
        float* bs = as + 128 * A_ST;
        #pragma unroll
        for (int i = 0; i < 4; i++) {
            int id = tid + 256 * i;
            int r = id >> 3, c = (id & 7) * 4;           // A: 128 x 32
            cpa(&as[r * A_ST + c], &A[(size_t)(row0 + r) * K + k0 + c]);
            int rb = id >> 5, nc = (id & 31) * 4;        // B: 32 x 128
            cpa(&bs[rb * B_ST + nc], &Bm[(size_t)(k0 + rb) * N + col0 + nc]);
        }
    };

    load_stage(0); cpcommit();

    for (int it = 0; it < nIter; it++) {
        if (it + 1 < nIter) load_stage(it + 1);   // overlaps wait+compute of it
        cpcommit();
        cpwait<1>();                              // stage it arrived
        __syncthreads();

        const float* as = sm + (it & 1) * STG_F;
        const float* bs = as + 128 * A_ST;
        #pragma unroll
        for (int k8 = 0; k8 < 4; k8++) {
            const int kk = k8 * 8;
            uint32_t a[4][4], b[4][2];
            #pragma unroll
            for (int mt = 0; mt < 4; mt++) {
                const int m = wm + mt * 16;
                a[mt][0] = __float_as_uint(as[(m + g    ) * A_ST + kk + tg]);
                a[mt][1] = __float_as_uint(as[(m + g + 8) * A_ST + kk + tg]);
                a[mt][2] = __float_as_uint(as[(m + g    ) * A_ST + kk + tg + 4]);
                a[mt][3] = __float_as_uint(as[(m + g + 8) * A_ST + kk + tg + 4]);
            }
            #pragma unroll
            for (int nt = 0; nt < 4; nt++) {
                const int n = wn + nt * 8;
                b[nt][0] = __float_as_uint(bs[(kk + tg    ) * B_ST + n + g]);
                b[nt][1] = __float_as_uint(bs[(kk + tg + 4) * B_ST + n + g]);
            }
            #pragma unroll
            for (int mt = 0; mt < 4; mt++)
                #pragma unroll
                for (int nt = 0; nt < 4; nt++)
                    mma8(acc[mt * 4 + nt], a[mt], b[nt]);
        }
        __syncthreads();   // all warps done with stage it before it+2 overwrites
    }

    #pragma unroll
    for (int mt = 0; mt < 4; mt++) {
        #pragma unroll
        for (int nt = 0; nt < 4; nt++) {
            int r = row0 + wm + mt * 16 + g;
            int c = col0 + wn + nt * 8 + 2 * tg;
            float v0 = acc[mt * 4 + nt][0], v1 = acc[mt * 4 + nt][1];
            float v2 = acc[mt * 4 + nt][2], v3 = acc[mt * 4 + nt][3];
            if (BIAS) {
                float b0 = bias[c], b1 = bias[c + 1];
                v0 += b0; v1 += b1; v2 += b0; v3 += b1;
            }
            if (ROUND) {
                v0 = to_tf32(v0); v1 = to_tf32(v1);
                v2 = to_tf32(v2); v3 = to_tf32(v3);
            }
            *(float2*)&C[(size_t)r * N + c]       = make_float2(v0, v1);
            *(float2*)&C[(size_t)(r + 8) * N + c] = make_float2(v2, v3);
        }
    }
}

// ---------------------------------------------------------------------------
// Flash attention (tf32 mma) — byte-for-byte the R3 version (known 2 CTA/SM).
//   out = sum(e^{s-m}*mask*v) / (sum(e^{s-m}*mask) + eps*sum(e^{s-m}))
// Block: 128 q-rows x one (b,h); 8 warps, warp owns 16 q-rows (softmax
// fully warp-local). 64 keys per iteration.
// ---------------------------------------------------------------------------
#define QS_OFF 0            // [128][68]
#define KS_OFF 8704         // [64][68]
#define VS_OFF 13056        // [64][72]
#define PS_OFF 17664        // [128][68]
#define ATTN_SMEM (26368 * 4)

__global__ __launch_bounds__(256)
void attn_mma(const float* __restrict__ qkv, const float* __restrict__ mask,
              float* __restrict__ z)
{
    extern __shared__ float sm[];
    float* Qs = sm + QS_OFF;
    float* Ks = sm + KS_OFF;
    float* Vs = sm + VS_OFF;
    float* Ps = sm + PS_OFF;

    const int tid = threadIdx.x;
    const int w = tid >> 5, lane = tid & 31;
    const int g = lane >> 2, tg = lane & 3;
    const int m0 = w * 16;
    const int bb = blockIdx.y >> 4;
    const int h  = blockIdx.y & 15;
    const int qi0 = blockIdx.x * 128;
    const size_t tok0 = (size_t)bb * L_ + qi0;
    const int hc = h * 64;

    // load Q tile: 128 x 64
    #pragma unroll
    for (int i = 0; i < 8; i++) {
        int id = tid + 256 * i;
        int r = id >> 4, dc = (id & 15) * 4;
        float4 v = *(const float4*)&qkv[(tok0 + r) * N3_ + hc + dc];
        *(float4*)&Qs[r * 68 + dc] = v;
    }

    float acc[8][4];
    #pragma unroll
    for (int i = 0; i < 8; i++)
        #pragma unroll
        for (int j = 0; j < 4; j++) acc[i][j] = 0.f;
    float mp0 = -1e30f, mp1 = -1e30f;
    float se0 = 0.f, se1 = 0.f, sq0 = 0.f, sq1 = 0.f;

    const float* mrow0 = mask + (tok0 + m0 + g) * L_ + 2 * tg;
    const float* mrow1 = mrow0 + 8 * (size_t)L_;

    for (int kt = 0; kt < L_ / 64; kt++) {
        const int kj0 = kt * 64;
        const size_t ktok = (size_t)bb * L_ + kj0;
        __syncthreads();                       // prior PV done
        #pragma unroll
        for (int i = 0; i < 4; i++) {
            int id = tid + 256 * i;
            int r = id >> 4, dc = (id & 15) * 4;
            float4 kv = *(const float4*)&qkv[(ktok + r) * N3_ + 1024 + hc + dc];
            *(float4*)&Ks[r * 68 + dc] = kv;
            float4 vv = *(const float4*)&qkv[(ktok + r) * N3_ + 2048 + hc + dc];
            *(float4*)&Vs[r * 72 + dc] = vv;
        }
        __syncthreads();

        // S = Q @ K^T : warp m16 x n64, 8 k-steps
        float s[8][4];
        #pragma unroll
        for (int nt = 0; nt < 8; nt++)
            #pragma unroll
            for (int j = 0; j < 4; j++) s[nt][j] = 0.f;
        #pragma unroll
        for (int k8 = 0; k8 < 8; k8++) {
            const int kk = k8 * 8;
            uint32_t a[4];
            a[0] = __float_as_uint(Qs[(m0 + g    ) * 68 + kk + tg]);
            a[1] = __float_as_uint(Qs[(m0 + g + 8) * 68 + kk + tg]);
            a[2] = __float_as_uint(Qs[(m0 + g    ) * 68 + kk + tg + 4]);
            a[3] = __float_as_uint(Qs[(m0 + g + 8) * 68 + kk + tg + 4]);
            #pragma unroll
            for (int nt = 0; nt < 8; nt++) {
                uint32_t b[2];
                b[0] = __float_as_uint(Ks[(nt * 8 + g) * 68 + kk + tg]);
                b[1] = __float_as_uint(Ks[(nt * 8 + g) * 68 + kk + tg + 4]);
                mma8(s[nt], a, b);
            }
        }

        // warp-local online softmax (rows g and g+8 of this warp)
        float r0 = -1e30f, r1 = -1e30f;
        #pragma unroll
        for (int nt = 0; nt < 8; nt++) {
            s[nt][0] *= 0.125f; s[nt][1] *= 0.125f;
            s[nt][2] *= 0.125f; s[nt][3] *= 0.125f;
            r0 = fmaxf(r0, fmaxf(s[nt][0], s[nt][1]));
            r1 = fmaxf(r1, fmaxf(s[nt][2], s[nt][3]));
        }
        r0 = fmaxf(r0, __shfl_xor_sync(0xffffffffu, r0, 1));
        r0 = fmaxf(r0, __shfl_xor_sync(0xffffffffu, r0, 2));
        r1 = fmaxf(r1, __shfl_xor_sync(0xffffffffu, r1, 1));
        r1 = fmaxf(r1, __shfl_xor_sync(0xffffffffu, r1, 2));

        float mn0 = fmaxf(mp0, r0), mn1 = fmaxf(mp1, r1);
        float c0 = fexp(mp0 - mn0), c1 = fexp(mp1 - mn1);
        mp0 = mn0; mp1 = mn1;

        float pe0 = 0.f, pe1 = 0.f, pm0 = 0.f, pm1 = 0.f;
        #pragma unroll
        for (int nt = 0; nt < 8; nt++) {
            const int mc = kj0 + nt * 8;
            float2 mk0 = *(const float2*)&mrow0[mc];
            float2 mk1 = *(const float2*)&mrow1[mc];
            float p00 = fexp(s[nt][0] - mn0);
            float p01 = fexp(s[nt][1] - mn0);
            float p10 = fexp(s[nt][2] - mn1);
            float p11 = fexp(s[nt][3] - mn1);
            pe0 += p00 + p01; pe1 += p10 + p11;
            float q00 = p00 * mk0.x, q01 = p01 * mk0.y;
            float q10 = p10 * mk1.x, q11 = p11 * mk1.y;
            pm0 += q00 + q01; pm1 += q10 + q11;
            *(float2*)&Ps[(m0 + g    ) * 68 + nt * 8 + 2 * tg] =
                make_float2(to_tf32(q00), to_tf32(q01));
            *(float2*)&Ps[(m0 + g + 8) * 68 + nt * 8 + 2 * tg] =
                make_float2(to_tf32(q10), to_tf32(q11));
        }
        pe0 += __shfl_xor_sync(0xffffffffu, pe0, 1);
        pe0 += __shfl_xor_sync(0xffffffffu, pe0, 2);
        pe1 += __shfl_xor_sync(0xffffffffu, pe1, 1);
        pe1 += __shfl_xor_sync(0xffffffffu, pe1, 2);
        pm0 += __shfl_xor_sync(0xffffffffu, pm0, 1);
        pm0 += __shfl_xor_sync(0xffffffffu, pm0, 2);
        pm1 += __shfl_xor_sync(0xffffffffu, pm1, 1);
        pm1 += __shfl_xor_sync(0xffffffffu, pm1, 2);
        se0 = se0 * c0 + pe0; se1 = se1 * c1 + pe1;
        sq0 = sq0 * c0 + pm0; sq1 = sq1 * c1 + pm1;
        #pragma unroll
        for (int nt = 0; nt < 8; nt++) {
            acc[nt][0] *= c0; acc[nt][1] *= c0;
            acc[nt][2] *= c1; acc[nt][3] *= c1;
        }
        __syncwarp();   // Ps is warp-private: warp-level fence suffices

        // acc += P @ V : m16 x n64(dh), k = 64 keys
        #pragma unroll
        for (int k8 = 0; k8 < 8; k8++) {
            const int kk = k8 * 8;
            uint32_t a[4];
            a[0] = __float_as_uint(Ps[(m0 + g    ) * 68 + kk + tg]);
            a[1] = __float_as_uint(Ps[(m0 + g + 8) * 68 + kk + tg]);
            a[2] = __float_as_uint(Ps[(m0 + g    ) * 68 + kk + tg + 4]);
            a[3] = __float_as_uint(Ps[(m0 + g + 8) * 68 + kk + tg + 4]);
            #pragma unroll
            for (int nt = 0; nt < 8; nt++) {
                uint32_t b[2];
                b[0] = __float_as_uint(Vs[(kk + tg    ) * 72 + nt * 8 + g]);
                b[1] = __float_as_uint(Vs[(kk + tg + 4) * 72 + nt * 8 + g]);
                mma8(acc[nt], a, b);
            }
        }
    }

    // epilogue: renorm, tf32-round for out-proj, write z[token][h*64+d]
    float inv0 = 1.0f / (sq0 + 1e-10f * se0 + 1e-30f);
    float inv1 = 1.0f / (sq1 + 1e-10f * se1 + 1e-30f);
    #pragma unroll
    for (int nt = 0; nt < 8; nt++) {
        int c = hc + nt * 8 + 2 * tg;
        *(float2*)&z[(tok0 + m0 + g) * D_ + c] =
            make_float2(to_tf32(acc[nt][0] * inv0), to_tf32(acc[nt][1] * inv0));
        *(float2*)&z[(tok0 + m0 + g + 8) * D_ + c] =
            make_float2(to_tf32(acc[nt][2] * inv1), to_tf32(acc[nt][3] * inv1));
    }
}

// ---------------------------------------------------------------------------
extern "C" void kernel_launch(void* const* d_in, const int* in_sizes, int n_in,
                              void* d_out, int out_size)
{
    const float* x    = (const float*)d_in[0];
    const float* mask = (const float*)d_in[1];
    const float* Wqkv = (const float*)d_in[2];
    const float* Wout = (const float*)d_in[3];
    const float* bout = (const float*)d_in[4];
    float* out = (float*)d_out;

    float *qkvp, *zp, *xr, *wq, *wo;
    cudaGetSymbolAddress((void**)&qkvp, g_qkv);
    cudaGetSymbolAddress((void**)&zp,   g_z);
    cudaGetSymbolAddress((void**)&xr,   g_xr);
    cudaGetSymbolAddress((void**)&wq,   g_wq);
    cudaGetSymbolAddress((void**)&wo,   g_wo);

    cudaFuncSetAttribute(mma_gemm<false, true>,
                         cudaFuncAttributeMaxDynamicSharedMemorySize, GEMM_SMEM);
    cudaFuncSetAttribute(mma_gemm<true, false>,
                         cudaFuncAttributeMaxDynamicSharedMemorySize, GEMM_SMEM);
    cudaFuncSetAttribute(attn_mma,
                         cudaFuncAttributeMaxDynamicSharedMemorySize, ATTN_SMEM);

    // 0) pre-round operands to tf32 (RNA) — mma loops stay convert-free
    {
        int n4x = MT_ * D_ / 4, n4q = D_ * N3_ / 4, n4o = D_ * D_ / 4;
        tf32_round<<<(n4x + 255) / 256, 256>>>((const float4*)x,    (float4*)xr, n4x);
        tf32_round<<<(n4q + 255) / 256, 256>>>((const float4*)Wqkv, (float4*)wq, n4q);
        tf32_round<<<(n4o + 255) / 256, 256>>>((const float4*)Wout, (float4*)wo, n4o);
    }

    // 1) QKV projection (epilogue rounds output for attention)
    mma_gemm<false, true><<<dim3(N3_ / 128, MT_ / 128), 256, GEMM_SMEM>>>(
        xr, wq, nullptr, qkvp, MT_, N3_, D_);

    // 2) masked flash attention (writes tf32-rounded z)
    attn_mma<<<dim3(L_ / 128, B_ * H_), 256, ATTN_SMEM>>>(qkvp, mask, zp);

    // 3) output projection + bias (exact fp32 output)
    mma_gemm<true, false><<<dim3(D_ / 128, MT_ / 128), 256, GEMM_SMEM>>>(
        zp, wo, bout, out, MT_, D_, D_);
}

// round 10
// speedup vs baseline: 2.1582x; 1.2055x over previous
#include <cuda_runtime.h>
#include <cuda_fp16.h>
#include <stdint.h>

#define B_   2
#define L_   2048
#define D_   1024
#define H_   16
#define N3_  3072
#define MT_  4096
#define LOG2E 1.4426950408889634f

// scratch (allocation-free rule: device globals)
__device__ float g_qkv[(size_t)MT_ * N3_];            // fp32 qkv (GEMM out)
__device__ float g_z[(size_t)MT_ * D_];               // tf32-rounded attn out
__device__ float g_xr[(size_t)MT_ * D_];              // tf32-rounded x
__device__ float g_wq[(size_t)D_ * N3_];              // tf32-rounded W_qkv
__device__ float g_wo[(size_t)D_ * D_];               // tf32-rounded W_out
// 16B-aligned: uint4 / cp.async.16 access these (half type alone aligns to 2!)
__device__ __align__(256) __half g_qkh[(size_t)MT_ * 2048];   // Q|K fp16
__device__ __align__(256) __half g_vt[(size_t)32 * 64 * L_];  // V^T fp16

__device__ __forceinline__ uint32_t tf32u(float x) {
    uint32_t u; asm("cvt.rna.tf32.f32 %0, %1;" : "=r"(u) : "f"(x));
    return u;
}
__device__ __forceinline__ float to_tf32(float x) {
    return __uint_as_float(tf32u(x));
}
// pack (lo, hi) floats -> f16x2 (lo in low half)
__device__ __forceinline__ uint32_t h2pack(float lo, float hi) {
    uint32_t r; asm("cvt.rn.f16x2.f32 %0, %1, %2;" : "=r"(r) : "f"(hi), "f"(lo));
    return r;
}

__device__ __forceinline__ void mma8(float* d, const uint32_t* a, const uint32_t* b) {
    asm volatile(
        "mma.sync.aligned.m16n8k8.row.col.f32.tf32.tf32.f32 "
        "{%0,%1,%2,%3}, {%4,%5,%6,%7}, {%8,%9}, {%0,%1,%2,%3};\n"
        : "+f"(d[0]), "+f"(d[1]), "+f"(d[2]), "+f"(d[3])
        : "r"(a[0]), "r"(a[1]), "r"(a[2]), "r"(a[3]), "r"(b[0]), "r"(b[1]));
}
__device__ __forceinline__ void mma16(float* d, const uint32_t* a, const uint32_t* b) {
    asm volatile(
        "mma.sync.aligned.m16n8k16.row.col.f32.f16.f16.f32 "
        "{%0,%1,%2,%3}, {%4,%5,%6,%7}, {%8,%9}, {%0,%1,%2,%3};\n"
        : "+f"(d[0]), "+f"(d[1]), "+f"(d[2]), "+f"(d[3])
        : "r"(a[0]), "r"(a[1]), "r"(a[2]), "r"(a[3]), "r"(b[0]), "r"(b[1]));
}

// cp.async helpers
__device__ __forceinline__ void cpa(void* s, const void* g) {
    uint32_t sa = (uint32_t)__cvta_generic_to_shared(s);
    asm volatile("cp.async.cg.shared.global [%0], [%1], 16;\n" :: "r"(sa), "l"(g));
}
__device__ __forceinline__ void cpcommit() { asm volatile("cp.async.commit_group;\n"); }
template<int N> __device__ __forceinline__ void cpwait() {
    asm volatile("cp.async.wait_group %0;\n" :: "n"(N));
}

// fast exp on FMA/ALU pipes. x <= 0 here.
__device__ __forceinline__ float fexp(float x) {
    x = fmaxf(x, -80.0f);
    float t = fmaf(x, LOG2E, 12582912.0f);
    float n = t - 12582912.0f;
    float f = fmaf(x, LOG2E, -n);
    float p = 1.3333558e-3f;
    p = fmaf(p, f, 9.6181291e-3f);
    p = fmaf(p, f, 5.5504109e-2f);
    p = fmaf(p, f, 2.4022651e-1f);
    p = fmaf(p, f, 6.9314718e-1f);
    p = fmaf(p, f, 1.0f);
    int ni = __float_as_int(t) - 0x4B400000;
    return __int_as_float(__float_as_int(p) + (ni << 23));
}

// ---------------------------------------------------------------------------
// tf32 pre-rounding pass
// ---------------------------------------------------------------------------
__global__ void tf32_round(const float4* __restrict__ in, float4* __restrict__ out, int n4) {
    int i = blockIdx.x * 256 + threadIdx.x;
    if (i < n4) {
        float4 v = in[i];
        v.x = to_tf32(v.x); v.y = to_tf32(v.y);
        v.z = to_tf32(v.z); v.w = to_tf32(v.w);
        out[i] = v;
    }
}

// ---------------------------------------------------------------------------
// Q|K fp32 -> fp16 pack:  g_qkh[token][c] = f16(qkv[token][c]), c < 2048
// ---------------------------------------------------------------------------
__global__ void qk_to_f16(const float* __restrict__ qkv, __half* __restrict__ qkh) {
    int i = (blockIdx.x * 256 + threadIdx.x) * 8;   // index in [token][2048] space
    int t = i >> 11, c = i & 2047;
    const float4* src = (const float4*)&qkv[(size_t)t * N3_ + c];
    float4 v0 = src[0], v1 = src[1];
    uint4 o;
    o.x = h2pack(v0.x, v0.y); o.y = h2pack(v0.z, v0.w);
    o.z = h2pack(v1.x, v1.y); o.w = h2pack(v1.z, v1.w);
    *(uint4*)&qkh[i] = o;
}

// ---------------------------------------------------------------------------
// V transpose: qkv V-part [token][dh] fp32 -> vt[bh][dh][token] fp16
// ts stride 68 floats = 272 B (multiple of 16 — float4 row stores aligned).
// ---------------------------------------------------------------------------
__global__ void v_transpose(const float* __restrict__ qkv, __half* __restrict__ vt) {
    __shared__ float ts[64][68];
    const int bh = blockIdx.x;             // b*16 + h
    const int t0 = blockIdx.y * 64;
    const int b = bh >> 4, hc = (bh & 15) * 64;
    const int tid = threadIdx.x;

    int r = tid >> 2, c0 = (tid & 3) * 16;     // ts[token][dh]
    #pragma unroll
    for (int j = 0; j < 4; j++) {
        float4 v = *(const float4*)&qkv[(size_t)(b * L_ + t0 + r) * N3_ + 2048 + hc + c0 + 4 * j];
        *(float4*)&ts[r][c0 + 4 * j] = v;
    }
    __syncthreads();

    int dh = tid & 63, k0 = (tid >> 6) * 16;   // 16 tokens per thread
    uint4 o0, o1;                              // build uint4 directly (alignment)
    o0.x = h2pack(ts[k0 +  0][dh], ts[k0 +  1][dh]);
    o0.y = h2pack(ts[k0 +  2][dh], ts[k0 +  3][dh]);
    o0.z = h2pack(ts[k0 +  4][dh], ts[k0 +  5][dh]);
    o0.w = h2pack(ts[k0 +  6][dh], ts[k0 +  7][dh]);
    o1.x = h2pack(ts[k0 +  8][dh], ts[k0 +  9][dh]);
    o1.y = h2pack(ts[k0 + 10][dh], ts[k0 + 11][dh]);
    o1.z = h2pack(ts[k0 + 12][dh], ts[k0 + 13][dh]);
    o1.w = h2pack(ts[k0 + 14][dh], ts[k0 + 15][dh]);
    size_t vrow = ((size_t)bh * 64 + dh) * L_ + t0 + k0;
    *(uint4*)&vt[vrow]     = o0;
    *(uint4*)&vt[vrow + 8] = o1;
}

// ---------------------------------------------------------------------------
// tf32 mma GEMM (R6, known-good): 2-stage cp.async, KC=32, 128x128 tile.
// ---------------------------------------------------------------------------
#define KC 32
#define A_ST 36
#define B_ST 136
#define STG_F (128 * A_ST + KC * B_ST)
#define GEMM_SMEM (2 * STG_F * 4)

template<bool BIAS, bool ROUND>
__global__ __launch_bounds__(256, 2)
void mma_gemm(const float* __restrict__ A, const float* __restrict__ Bm,
              const float* __restrict__ bias, float* __restrict__ C,
              int M, int N, int K)
{
    extern __shared__ float sm[];
    const int tid  = threadIdx.x;
    const int w    = tid >> 5, lane = tid & 31;
    const int g    = lane >> 2, tg = lane & 3;
    const int wm   = (w >> 2) * 64;
    const int wn   = (w & 3) * 32;
    const int row0 = blockIdx.y * 128, col0 = blockIdx.x * 128;

    float acc[16][4];
    #pragma unroll
    for (int i = 0; i < 16; i++)
        #pragma unroll
        for (int j = 0; j < 4; j++) acc[i][j] = 0.f;

    const int nIter = K / KC;

    auto load_stage = [&](int it) {
        const int k0 = it * KC;
        float* as = sm + (it & 1) * STG_F;
        float* bs = as + 128 * A_ST;
        #pragma unroll
        for (int i = 0; i < 4; i++) {
            int id = tid + 256 * i;
            int r = id >> 3, c = (id & 7) * 4;
            cpa(&as[r * A_ST + c], &A[(size_t)(row0 + r) * K + k0 + c]);
            int rb = id >> 5, nc = (id & 31) * 4;
            cpa(&bs[rb * B_ST + nc], &Bm[(size_t)(k0 + rb) * N + col0 + nc]);
        }
    };

    load_stage(0); cpcommit();

    for (int it = 0; it < nIter; it++) {
        if (it + 1 < nIter) load_stage(it + 1);
        cpcommit();
        cpwait<1>();
        __syncthreads();

        const float* as = sm + (it & 1) * STG_F;
        const float* bs = as + 128 * A_ST;
        #pragma unroll
        for (int k8 = 0; k8 < 4; k8++) {
            const int kk = k8 * 8;
            uint32_t a[4][4], b[4][2];
            #pragma unroll
            for (int mt = 0; mt < 4; mt++) {
                const int m = wm + mt * 16;
                a[mt][0] = __float_as_uint(as[(m + g    ) * A_ST + kk + tg]);
                a[mt][1] = __float_as_uint(as[(m + g + 8) * A_ST + kk + tg]);
                a[mt][2] = __float_as_uint(as[(m + g    ) * A_ST + kk + tg + 4]);
                a[mt][3] = __float_as_uint(as[(m + g + 8) * A_ST + kk + tg + 4]);
            }
            #pragma unroll
            for (int nt = 0; nt < 4; nt++) {
                const int n = wn + nt * 8;
                b[nt][0] = __float_as_uint(bs[(kk + tg    ) * B_ST + n + g]);
                b[nt][1] = __float_as_uint(bs[(kk + tg + 4) * B_ST + n + g]);
            }
            #pragma unroll
            for (int mt = 0; mt < 4; mt++)
                #pragma unroll
                for (int nt = 0; nt < 4; nt++)
                    mma8(acc[mt * 4 + nt], a[mt], b[nt]);
        }
        __syncthreads();
    }

    #pragma unroll
    for (int mt = 0; mt < 4; mt++) {
        #pragma unroll
        for (int nt = 0; nt < 4; nt++) {
            int r = row0 + wm + mt * 16 + g;
            int c = col0 + wn + nt * 8 + 2 * tg;
            float v0 = acc[mt * 4 + nt][0], v1 = acc[mt * 4 + nt][1];
            float v2 = acc[mt * 4 + nt][2], v3 = acc[mt * 4 + nt][3];
            if (BIAS) {
                float b0 = bias[c], b1 = bias[c + 1];
                v0 += b0; v1 += b1; v2 += b0; v3 += b1;
            }
            if (ROUND) {
                v0 = to_tf32(v0); v1 = to_tf32(v1);
                v2 = to_tf32(v2); v3 = to_tf32(v3);
            }
            *(float2*)&C[(size_t)r * N + c]       = make_float2(v0, v1);
            *(float2*)&C[(size_t)(r + 8) * N + c] = make_float2(v2, v3);
        }
    }
}

// ---------------------------------------------------------------------------
// Flash attention, fp16 mma (m16n8k16, f32 accum), fp32 softmax state.
// fp16 mantissa (10 bits) == tf32 mantissa -> same numerics as the R6 tf32
// attention (measured 6.76e-4), at half the LDS bytes and mma count.
//   out = sum(e^{s-m}*mask*v) / (sum(e^{s-m}*mask) + eps*sum(e^{s-m}))
// Block: 128 q-rows x one (b,h); warp owns 16 q-rows (softmax warp-local).
// P stays in registers (f16x2) — the m16n8k16 A-fragment for lane (g,tg) at
// K-step ks is exactly the q-pairs this lane computed at nt=2ks, 2ks+1.
// K and V^T tiles double-buffered via cp.async. All smem fp16, stride 72.
// ---------------------------------------------------------------------------
#define QS_B 0                            // Qs: 128*72*2 = 18432 B
#define KS_B 18432                        // Ks: 2 x 64*72*2
#define VT_B (18432 + 18432)              // Vt: 2 x 64*72*2
#define ATTN_SMEM (VT_B + 18432)          // 55296 B

__global__ __launch_bounds__(256)
void attn_mma(const __half* __restrict__ qkh,
              const __half* __restrict__ vtg,
              const float* __restrict__ mask, float* __restrict__ z)
{
    extern __shared__ char smc[];
    __half* Qs = (__half*)(smc + QS_B);

    const int tid = threadIdx.x;
    const int w = tid >> 5, lane = tid & 31;
    const int g = lane >> 2, tg = lane & 3;
    const int m0 = w * 16;
    const int bb = blockIdx.y >> 4;
    const int h  = blockIdx.y & 15;
    const int qi0 = blockIdx.x * 128;
    const size_t tok0 = (size_t)bb * L_ + qi0;
    const int hc = h * 64;

    auto load_kv = [&](int kt) {
        __half* ks = (__half*)(smc + KS_B + (kt & 1) * 9216);
        __half* vs = (__half*)(smc + VT_B + (kt & 1) * 9216);
        int r = tid >> 2, c0 = (tid & 3) * 16;
        const size_t ktok = (size_t)bb * L_ + kt * 64;
        cpa(&ks[r * 72 + c0],     &qkh[(ktok + r) * 2048 + 1024 + hc + c0]);
        cpa(&ks[r * 72 + c0 + 8], &qkh[(ktok + r) * 2048 + 1024 + hc + c0 + 8]);
        const size_t vrow = ((size_t)(bb * 16 + h) * 64 + r) * L_ + kt * 64;
        cpa(&vs[r * 72 + c0],     &vtg[vrow + c0]);
        cpa(&vs[r * 72 + c0 + 8], &vtg[vrow + c0 + 8]);
    };

    // prologue: Q + K/V(0) in group 0; K/V(1) in group 1
    {
        int r = tid >> 1, c0 = (tid & 1) * 32;
        #pragma unroll
        for (int j = 0; j < 4; j++)
            cpa(&Qs[r * 72 + c0 + 8 * j], &qkh[(tok0 + r) * 2048 + hc + c0 + 8 * j]);
    }
    load_kv(0); cpcommit();
    load_kv(1); cpcommit();

    float acc[8][4];
    #pragma unroll
    for (int i = 0; i < 8; i++)
        #pragma unroll
        for (int j = 0; j < 4; j++) acc[i][j] = 0.f;
    float mp0 = -1e30f, mp1 = -1e30f;
    float se0 = 0.f, se1 = 0.f, sq0 = 0.f, sq1 = 0.f;

    const float* mrow0 = mask + (tok0 + m0 + g) * L_ + 2 * tg;
    const float* mrow1 = mrow0 + 8 * (size_t)L_;
    const int qrow0 = (m0 + g) * 72, qrow1 = (m0 + g + 8) * 72;

    for (int kt = 0; kt < L_ / 64; kt++) {
        const int kj0 = kt * 64;
        cpwait<1>();
        __syncthreads();                 // tile kt (and Q on kt=0) resident
        const __half* Ks = (const __half*)(smc + KS_B + (kt & 1) * 9216);
        const __half* Vs = (const __half*)(smc + VT_B + (kt & 1) * 9216);

        // S = Q @ K^T : m16 x n64, fp16 k16 x 4 steps
        float s[8][4];
        #pragma unroll
        for (int nt = 0; nt < 8; nt++)
            #pragma unroll
            for (int j = 0; j < 4; j++) s[nt][j] = 0.f;
        #pragma unroll
        for (int ks = 0; ks < 4; ks++) {
            const int kk = ks * 16 + 2 * tg;
            uint32_t a[4];
            a[0] = *(const uint32_t*)&Qs[qrow0 + kk];
            a[1] = *(const uint32_t*)&Qs[qrow1 + kk];
            a[2] = *(const uint32_t*)&Qs[qrow0 + kk + 8];
            a[3] = *(const uint32_t*)&Qs[qrow1 + kk + 8];
            #pragma unroll
            for (int nt = 0; nt < 8; nt++) {
                uint32_t b[2];
                b[0] = *(const uint32_t*)&Ks[(nt * 8 + g) * 72 + kk];
                b[1] = *(const uint32_t*)&Ks[(nt * 8 + g) * 72 + kk + 8];
                mma16(s[nt], a, b);
            }
        }

        // warp-local online softmax (rows g and g+8 of this warp)
        float r0 = -1e30f, r1 = -1e30f;
        #pragma unroll
        for (int nt = 0; nt < 8; nt++) {
            s[nt][0] *= 0.125f; s[nt][1] *= 0.125f;
            s[nt][2] *= 0.125f; s[nt][3] *= 0.125f;
            r0 = fmaxf(r0, fmaxf(s[nt][0], s[nt][1]));
            r1 = fmaxf(r1, fmaxf(s[nt][2], s[nt][3]));
        }
        r0 = fmaxf(r0, __shfl_xor_sync(0xffffffffu, r0, 1));
        r0 = fmaxf(r0, __shfl_xor_sync(0xffffffffu, r0, 2));
        r1 = fmaxf(r1, __shfl_xor_sync(0xffffffffu, r1, 1));
        r1 = fmaxf(r1, __shfl_xor_sync(0xffffffffu, r1, 2));

        float mn0 = fmaxf(mp0, r0), mn1 = fmaxf(mp1, r1);
        float c0 = fexp(mp0 - mn0), c1 = fexp(mp1 - mn1);
        mp0 = mn0; mp1 = mn1;

        uint32_t p0[8], p1[8];     // masked P, f16x2, rows g / g+8
        float pe0 = 0.f, pe1 = 0.f, pm0 = 0.f, pm1 = 0.f;
        #pragma unroll
        for (int nt = 0; nt < 8; nt++) {
            const int mc = kj0 + nt * 8;
            float2 mk0 = *(const float2*)&mrow0[mc];
            float2 mk1 = *(const float2*)&mrow1[mc];
            float p00 = fexp(s[nt][0] - mn0);
            float p01 = fexp(s[nt][1] - mn0);
            float p10 = fexp(s[nt][2] - mn1);
            float p11 = fexp(s[nt][3] - mn1);
            pe0 += p00 + p01; pe1 += p10 + p11;
            float q00 = p00 * mk0.x, q01 = p01 * mk0.y;
            float q10 = p10 * mk1.x, q11 = p11 * mk1.y;
            pm0 += q00 + q01; pm1 += q10 + q11;
            p0[nt] = h2pack(q00, q01);
            p1[nt] = h2pack(q10, q11);
        }
        pe0 += __shfl_xor_sync(0xffffffffu, pe0, 1);
        pe0 += __shfl_xor_sync(0xffffffffu, pe0, 2);
        pe1 += __shfl_xor_sync(0xffffffffu, pe1, 1);
        pe1 += __shfl_xor_sync(0xffffffffu, pe1, 2);
        pm0 += __shfl_xor_sync(0xffffffffu, pm0, 1);
        pm0 += __shfl_xor_sync(0xffffffffu, pm0, 2);
        pm1 += __shfl_xor_sync(0xffffffffu, pm1, 1);
        pm1 += __shfl_xor_sync(0xffffffffu, pm1, 2);
        se0 = se0 * c0 + pe0; se1 = se1 * c1 + pe1;
        sq0 = sq0 * c0 + pm0; sq1 = sq1 * c1 + pm1;
        #pragma unroll
        for (int nt = 0; nt < 8; nt++) {
            acc[nt][0] *= c0; acc[nt][1] *= c0;
            acc[nt][2] *= c1; acc[nt][3] *= c1;
        }

        // acc += P @ V : m16 x n64(dh), k = 64 keys, P from registers
        #pragma unroll
        for (int ks = 0; ks < 4; ks++) {
            uint32_t a[4];
            a[0] = p0[2 * ks];     a[1] = p1[2 * ks];
            a[2] = p0[2 * ks + 1]; a[3] = p1[2 * ks + 1];
            const int kk = ks * 16 + 2 * tg;
            #pragma unroll
            for (int nt = 0; nt < 8; nt++) {
                uint32_t b[2];
                b[0] = *(const uint32_t*)&Vs[(nt * 8 + g) * 72 + kk];
                b[1] = *(const uint32_t*)&Vs[(nt * 8 + g) * 72 + kk + 8];
                mma16(acc[nt], a, b);
            }
        }

        __syncthreads();                 // all warps done with buffer kt&1
        if (kt + 2 < L_ / 64) load_kv(kt + 2);
        cpcommit();
    }

    // epilogue: renorm, tf32-round for out-proj, write z[token][h*64+d]
    float inv0 = 1.0f / (sq0 + 1e-10f * se0 + 1e-30f);
    float inv1 = 1.0f / (sq1 + 1e-10f * se1 + 1e-30f);
    #pragma unroll
    for (int nt = 0; nt < 8; nt++) {
        int c = hc + nt * 8 + 2 * tg;
        *(float2*)&z[(tok0 + m0 + g) * D_ + c] =
            make_float2(to_tf32(acc[nt][0] * inv0), to_tf32(acc[nt][1] * inv0));
        *(float2*)&z[(tok0 + m0 + g + 8) * D_ + c] =
            make_float2(to_tf32(acc[nt][2] * inv1), to_tf32(acc[nt][3] * inv1));
    }
}

// ---------------------------------------------------------------------------
extern "C" void kernel_launch(void* const* d_in, const int* in_sizes, int n_in,
                              void* d_out, int out_size)
{
    const float* x    = (const float*)d_in[0];
    const float* mask = (const float*)d_in[1];
    const float* Wqkv = (const float*)d_in[2];
    const float* Wout = (const float*)d_in[3];
    const float* bout = (const float*)d_in[4];
    float* out = (float*)d_out;

    float *qkvp, *zp, *xr, *wq, *wo;
    __half *qkh, *vt;
    cudaGetSymbolAddress((void**)&qkvp, g_qkv);
    cudaGetSymbolAddress((void**)&zp,   g_z);
    cudaGetSymbolAddress((void**)&xr,   g_xr);
    cudaGetSymbolAddress((void**)&wq,   g_wq);
    cudaGetSymbolAddress((void**)&wo,   g_wo);
    cudaGetSymbolAddress((void**)&qkh,  g_qkh);
    cudaGetSymbolAddress((void**)&vt,   g_vt);

    cudaFuncSetAttribute(mma_gemm<false, false>,
                         cudaFuncAttributeMaxDynamicSharedMemorySize, GEMM_SMEM);
    cudaFuncSetAttribute(mma_gemm<true, false>,
                         cudaFuncAttributeMaxDynamicSharedMemorySize, GEMM_SMEM);
    cudaFuncSetAttribute(attn_mma,
                         cudaFuncAttributeMaxDynamicSharedMemorySize, ATTN_SMEM);

    // 0) pre-round GEMM operands to tf32 (RNA)
    {
        int n4x = MT_ * D_ / 4, n4q = D_ * N3_ / 4, n4o = D_ * D_ / 4;
        tf32_round<<<(n4x + 255) / 256, 256>>>((const float4*)x,    (float4*)xr, n4x);
        tf32_round<<<(n4q + 255) / 256, 256>>>((const float4*)Wqkv, (float4*)wq, n4q);
        tf32_round<<<(n4o + 255) / 256, 256>>>((const float4*)Wout, (float4*)wo, n4o);
    }

    // 1) QKV projection (fp32 out; attention consumes fp16 versions)
    mma_gemm<false, false><<<dim3(N3_ / 128, MT_ / 128), 256, GEMM_SMEM>>>(
        xr, wq, nullptr, qkvp, MT_, N3_, D_);

    // 1b) fp16 packs: Q|K straight, V transposed per (b,h)
    qk_to_f16<<<MT_ * 2048 / (256 * 8), 256>>>(qkvp, qkh);
    v_transpose<<<dim3(32, L_ / 64), 256>>>(qkvp, vt);

    // 2) masked flash attention (fp16 mma, fp32 softmax; writes tf32 z)
    attn_mma<<<dim3(L_ / 128, B_ * H_), 256, ATTN_SMEM>>>(qkh, vt, mask, zp);

    // 3) output projection + bias (tf32 mma, exact fp32 output)
    mma_gemm<true, false><<<dim3(D_ / 128, MT_ / 128), 256, GEMM_SMEM>>>(
        zp, wo, bout, out, MT_, D_, D_);
}

// round 13
// speedup vs baseline: 2.6210x; 1.2145x over previous
#include <cuda_runtime.h>
#include <cuda_fp16.h>
#include <stdint.h>

#define B_   2
#define L_   2048
#define D_   1024
#define H_   16
#define N3_  3072
#define MT_  4096
#define LOG2E 1.4426950408889634f

// scratch (allocation-free rule: device globals); 16B+ aligned for uint4/cp.async
__device__ __align__(256) __half g_qkvh[(size_t)MT_ * N3_];   // fp16 qkv
__device__ __align__(256) __half g_vt[(size_t)32 * 64 * L_];  // V^T fp16
__device__ __align__(256) __half g_zh[(size_t)MT_ * D_];      // fp16 attn out
__device__ __align__(256) __half g_xh[(size_t)MT_ * D_];      // fp16 x
__device__ __align__(256) __half g_wqt[(size_t)N3_ * D_];     // W_qkv^T fp16
__device__ __align__(256) __half g_wot[(size_t)D_ * D_];      // W_out^T fp16

// pack (lo, hi) floats -> f16x2 (lo in low half)
__device__ __forceinline__ uint32_t h2pack(float lo, float hi) {
    uint32_t r; asm("cvt.rn.f16x2.f32 %0, %1, %2;" : "=r"(r) : "f"(hi), "f"(lo));
    return r;
}
__device__ __forceinline__ uint32_t hh(__half lo, __half hi) {
    __half2 t = __halves2half2(lo, hi);
    return *(uint32_t*)&t;
}

__device__ __forceinline__ void mma16(float* d, const uint32_t* a, const uint32_t* b) {
    asm volatile(
        "mma.sync.aligned.m16n8k16.row.col.f32.f16.f16.f32 "
        "{%0,%1,%2,%3}, {%4,%5,%6,%7}, {%8,%9}, {%0,%1,%2,%3};\n"
        : "+f"(d[0]), "+f"(d[1]), "+f"(d[2]), "+f"(d[3])
        : "r"(a[0]), "r"(a[1]), "r"(a[2]), "r"(a[3]), "r"(b[0]), "r"(b[1]));
}

// cp.async helpers
__device__ __forceinline__ void cpa(void* s, const void* g) {
    uint32_t sa = (uint32_t)__cvta_generic_to_shared(s);
    asm volatile("cp.async.cg.shared.global [%0], [%1], 16;\n" :: "r"(sa), "l"(g));
}
__device__ __forceinline__ void cpcommit() { asm volatile("cp.async.commit_group;\n"); }
template<int N> __device__ __forceinline__ void cpwait() {
    asm volatile("cp.async.wait_group %0;\n" :: "n"(N));
}

// fast exp on FMA/ALU pipes. x <= 0 here.
__device__ __forceinline__ float fexp(float x) {
    x = fmaxf(x, -80.0f);
    float t = fmaf(x, LOG2E, 12582912.0f);
    float n = t - 12582912.0f;
    float f = fmaf(x, LOG2E, -n);
    float p = 1.3333558e-3f;
    p = fmaf(p, f, 9.6181291e-3f);
    p = fmaf(p, f, 5.5504109e-2f);
    p = fmaf(p, f, 2.4022651e-1f);
    p = fmaf(p, f, 6.9314718e-1f);
    p = fmaf(p, f, 1.0f);
    int ni = __float_as_int(t) - 0x4B400000;
    return __int_as_float(__float_as_int(p) + (ni << 23));
}

// ---------------------------------------------------------------------------
// fp32 -> fp16 elementwise pack (contiguous buffer, 8 elems/thread)
// ---------------------------------------------------------------------------
__global__ void f32_to_f16(const float* __restrict__ in, __half* __restrict__ out) {
    int i = (blockIdx.x * 256 + threadIdx.x) * 8;
    float4 v0 = *(const float4*)&in[i], v1 = *(const float4*)&in[i + 4];
    uint4 o;
    o.x = h2pack(v0.x, v0.y); o.y = h2pack(v0.z, v0.w);
    o.z = h2pack(v1.x, v1.y); o.w = h2pack(v1.z, v1.w);
    *(uint4*)&out[i] = o;
}

// ---------------------------------------------------------------------------
// Transpose + fp16 pack: in fp32 [K][N] -> out fp16 [N][K]. 64x64 tiles.
// ts stride 68 floats = 272 B (mult of 16 -> aligned float4 stores).
// ---------------------------------------------------------------------------
__global__ void transpose_pack(const float* __restrict__ in, __half* __restrict__ out,
                               int K, int N) {
    __shared__ float ts[64][68];
    const int n0 = blockIdx.x * 64, k0 = blockIdx.y * 64;
    const int tid = threadIdx.x;

    int r = tid >> 2, c0 = (tid & 3) * 16;        // ts[k][n]
    #pragma unroll
    for (int j = 0; j < 4; j++) {
        float4 v = *(const float4*)&in[(size_t)(k0 + r) * N + n0 + c0 + 4 * j];
        *(float4*)&ts[r][c0 + 4 * j] = v;
    }
    __syncthreads();

    int n = tid & 63, kk = (tid >> 6) * 16;       // 16 k per thread
    uint4 o0, o1;
    o0.x = h2pack(ts[kk +  0][n], ts[kk +  1][n]);
    o0.y = h2pack(ts[kk +  2][n], ts[kk +  3][n]);
    o0.z = h2pack(ts[kk +  4][n], ts[kk +  5][n]);
    o0.w = h2pack(ts[kk +  6][n], ts[kk +  7][n]);
    o1.x = h2pack(ts[kk +  8][n], ts[kk +  9][n]);
    o1.y = h2pack(ts[kk + 10][n], ts[kk + 11][n]);
    o1.z = h2pack(ts[kk + 12][n], ts[kk + 13][n]);
    o1.w = h2pack(ts[kk + 14][n], ts[kk + 15][n]);
    size_t orow = (size_t)(n0 + n) * K + k0 + kk;
    *(uint4*)&out[orow]     = o0;
    *(uint4*)&out[orow + 8] = o1;
}

// ---------------------------------------------------------------------------
// V transpose: qkvh V-part fp16 [token][dh] -> vt[bh][dh][token] fp16
// ---------------------------------------------------------------------------
__global__ void v_transpose(const __half* __restrict__ qkvh, __half* __restrict__ vt) {
    __shared__ __half ts[64][72];
    const int bh = blockIdx.x;             // b*16 + h
    const int t0 = blockIdx.y * 64;
    const int b = bh >> 4, hc = (bh & 15) * 64;
    const int tid = threadIdx.x;

    #pragma unroll
    for (int i = 0; i < 2; i++) {
        int id = tid + 256 * i;                  // 0..511 chunks of 8 halves
        int row = id >> 3, c = (id & 7) * 8;
        *(uint4*)&ts[row][c] =
            *(const uint4*)&qkvh[(size_t)(b * L_ + t0 + row) * N3_ + 2048 + hc + c];
    }
    __syncthreads();

    int dh = tid & 63, k0 = (tid >> 6) * 16;     // 16 tokens per thread
    uint4 o0, o1;
    o0.x = hh(ts[k0 +  0][dh], ts[k0 +  1][dh]);
    o0.y = hh(ts[k0 +  2][dh], ts[k0 +  3][dh]);
    o0.z = hh(ts[k0 +  4][dh], ts[k0 +  5][dh]);
    o0.w = hh(ts[k0 +  6][dh], ts[k0 +  7][dh]);
    o1.x = hh(ts[k0 +  8][dh], ts[k0 +  9][dh]);
    o1.y = hh(ts[k0 + 10][dh], ts[k0 + 11][dh]);
    o1.z = hh(ts[k0 + 12][dh], ts[k0 + 13][dh]);
    o1.w = hh(ts[k0 + 14][dh], ts[k0 + 15][dh]);
    size_t vrow = ((size_t)bh * 64 + dh) * L_ + t0 + k0;
    *(uint4*)&vt[vrow]     = o0;
    *(uint4*)&vt[vrow + 8] = o1;
}

// ---------------------------------------------------------------------------
// fp16 mma GEMM: C[M,N] = A[M,K] @ Bt[N,K]^T, fp32 accum.
// 128x128 tile, K-chunk 32, 2-stage cp.async, 8 warps 2(m)x4(n).
// A and Bt both row-major with k contiguous -> natural f16x2 fragments.
// smem stride 40 halves (80 B = 20 banks): frag bank = (20g+tg)%32, bijective.
// OUTF16: write fp16 (no bias). else: +bias, fp32 out.
// ---------------------------------------------------------------------------
#define HKC 32
#define H_ST 40
#define HSTG (256 * H_ST)                 // halves per stage (A128 + B128 rows)
#define HGEMM_SMEM (2 * HSTG * 2)         // 40960 bytes

template<bool OUTF16>
__global__ __launch_bounds__(256, 2)
void hgemm(const __half* __restrict__ A, const __half* __restrict__ Bt,
           const float* __restrict__ bias, void* __restrict__ Cout,
           int M, int N, int K)
{
    extern __shared__ __half hsm[];
    const int tid  = threadIdx.x;
    const int w    = tid >> 5, lane = tid & 31;
    const int g    = lane >> 2, tg = lane & 3;
    const int wm   = (w >> 2) * 64;
    const int wn   = (w & 3) * 32;
    const int row0 = blockIdx.y * 128, col0 = blockIdx.x * 128;

    float acc[16][4];
    #pragma unroll
    for (int i = 0; i < 16; i++)
        #pragma unroll
        for (int j = 0; j < 4; j++) acc[i][j] = 0.f;

    const int nIter = K / HKC;

    auto load_stage = [&](int it) {
        const int k0 = it * HKC;
        __half* as = hsm + (it & 1) * HSTG;
        __half* bs = as + 128 * H_ST;
        #pragma unroll
        for (int i = 0; i < 2; i++) {
            int id = tid + 256 * i;               // 0..511 chunks (8 halves)
            int r = id >> 2, c = (id & 3) * 8;
            cpa(&as[r * H_ST + c], &A[(size_t)(row0 + r) * K + k0 + c]);
            cpa(&bs[r * H_ST + c], &Bt[(size_t)(col0 + r) * K + k0 + c]);
        }
    };

    load_stage(0); cpcommit();

    for (int it = 0; it < nIter; it++) {
        if (it + 1 < nIter) load_stage(it + 1);
        cpcommit();
        cpwait<1>();
        __syncthreads();

        const __half* as = hsm + (it & 1) * HSTG;
        const __half* bs = as + 128 * H_ST;
        #pragma unroll
        for (int ks = 0; ks < 2; ks++) {
            const int kk = ks * 16 + 2 * tg;
            uint32_t a[4][4], b[4][2];
            #pragma unroll
            for (int mt = 0; mt < 4; mt++) {
                const int m = wm + mt * 16;
                a[mt][0] = *(const uint32_t*)&as[(m + g    ) * H_ST + kk];
                a[mt][1] = *(const uint32_t*)&as[(m + g + 8) * H_ST + kk];
                a[mt][2] = *(const uint32_t*)&as[(m + g    ) * H_ST + kk + 8];
                a[mt][3] = *(const uint32_t*)&as[(m + g + 8) * H_ST + kk + 8];
            }
            #pragma unroll
            for (int nt = 0; nt < 4; nt++) {
                const int n = wn + nt * 8;
                b[nt][0] = *(const uint32_t*)&bs[(n + g) * H_ST + kk];
                b[nt][1] = *(const uint32_t*)&bs[(n + g) * H_ST + kk + 8];
            }
            #pragma unroll
            for (int mt = 0; mt < 4; mt++)
                #pragma unroll
                for (int nt = 0; nt < 4; nt++)
                    mma16(acc[mt * 4 + nt], a[mt], b[nt]);
        }
        __syncthreads();
    }

    #pragma unroll
    for (int mt = 0; mt < 4; mt++) {
        #pragma unroll
        for (int nt = 0; nt < 4; nt++) {
            int r = row0 + wm + mt * 16 + g;
            int c = col0 + wn + nt * 8 + 2 * tg;
            float v0 = acc[mt * 4 + nt][0], v1 = acc[mt * 4 + nt][1];
            float v2 = acc[mt * 4 + nt][2], v3 = acc[mt * 4 + nt][3];
            if (OUTF16) {
                __half* C = (__half*)Cout;
                *(uint32_t*)&C[(size_t)r * N + c]       = h2pack(v0, v1);
                *(uint32_t*)&C[(size_t)(r + 8) * N + c] = h2pack(v2, v3);
            } else {
                float* C = (float*)Cout;
                float b0 = bias[c], b1 = bias[c + 1];
                *(float2*)&C[(size_t)r * N + c]       = make_float2(v0 + b0, v1 + b1);
                *(float2*)&C[(size_t)(r + 8) * N + c] = make_float2(v2 + b0, v3 + b1);
            }
        }
    }
}

// ---------------------------------------------------------------------------
// Flash attention, fp16 mma (m16n8k16, f32 accum), fp32 softmax state.
//   out = sum(e^{s-m}*mask*v) / (sum(e^{s-m}*mask) + eps*sum(e^{s-m}))
// Block: 128 q-rows x one (b,h); warp owns 16 q-rows (softmax warp-local).
// P register-resident; K/V^T double-buffered via cp.async; smem stride 72.
// Writes z directly as fp16 (out-proj A operand).
// ---------------------------------------------------------------------------
#define QS_B 0                            // Qs: 128*72*2 = 18432 B
#define KS_B 18432                        // Ks: 2 x 64*72*2
#define VT_B (18432 + 18432)              // Vt: 2 x 64*72*2
#define ATTN_SMEM (VT_B + 18432)          // 55296 B

__global__ __launch_bounds__(256)
void attn_mma(const __half* __restrict__ qkvh,
              const __half* __restrict__ vtg,
              const float* __restrict__ mask, __half* __restrict__ z)
{
    extern __shared__ char smc[];
    __half* Qs = (__half*)(smc + QS_B);

    const int tid = threadIdx.x;
    const int w = tid >> 5, lane = tid & 31;
    const int g = lane >> 2, tg = lane & 3;
    const int m0 = w * 16;
    const int bb = blockIdx.y >> 4;
    const int h  = blockIdx.y & 15;
    const int qi0 = blockIdx.x * 128;
    const size_t tok0 = (size_t)bb * L_ + qi0;
    const int hc = h * 64;

    auto load_kv = [&](int kt) {
        __half* ks = (__half*)(smc + KS_B + (kt & 1) * 9216);
        __half* vs = (__half*)(smc + VT_B + (kt & 1) * 9216);
        int r = tid >> 2, c0 = (tid & 3) * 16;
        const size_t ktok = (size_t)bb * L_ + kt * 64;
        cpa(&ks[r * 72 + c0],     &qkvh[(ktok + r) * N3_ + 1024 + hc + c0]);
        cpa(&ks[r * 72 + c0 + 8], &qkvh[(ktok + r) * N3_ + 1024 + hc + c0 + 8]);
        const size_t vrow = ((size_t)(bb * 16 + h) * 64 + r) * L_ + kt * 64;
        cpa(&vs[r * 72 + c0],     &vtg[vrow + c0]);
        cpa(&vs[r * 72 + c0 + 8], &vtg[vrow + c0 + 8]);
    };

    // prologue: Q + K/V(0) in group 0; K/V(1) in group 1
    {
        int r = tid >> 1, c0 = (tid & 1) * 32;
        #pragma unroll
        for (int j = 0; j < 4; j++)
            cpa(&Qs[r * 72 + c0 + 8 * j], &qkvh[(tok0 + r) * N3_ + hc + c0 + 8 * j]);
    }
    load_kv(0); cpcommit();
    load_kv(1); cpcommit();

    float acc[8][4];
    #pragma unroll
    for (int i = 0; i < 8; i++)
        #pragma unroll
        for (int j = 0; j < 4; j++) acc[i][j] = 0.f;
    float mp0 = -1e30f, mp1 = -1e30f;
    float se0 = 0.f, se1 = 0.f, sq0 = 0.f, sq1 = 0.f;

    const float* mrow0 = mask + (tok0 + m0 + g) * L_ + 2 * tg;
    const float* mrow1 = mrow0 + 8 * (size_t)L_;
    const int qrow0 = (m0 + g) * 72, qrow1 = (m0 + g + 8) * 72;

    for (int kt = 0; kt < L_ / 64; kt++) {
        const int kj0 = kt * 64;
        cpwait<1>();
        __syncthreads();                 // tile kt (and Q on kt=0) resident
        const __half* Ks = (const __half*)(smc + KS_B + (kt & 1) * 9216);
        const __half* Vs = (const __half*)(smc + VT_B + (kt & 1) * 9216);

        // S = Q @ K^T : m16 x n64, fp16 k16 x 4 steps
        float s[8][4];
        #pragma unroll
        for (int nt = 0; nt < 8; nt++)
            #pragma unroll
            for (int j = 0; j < 4; j++) s[nt][j] = 0.f;
        #pragma unroll
        for (int ks = 0; ks < 4; ks++) {
            const int kk = ks * 16 + 2 * tg;
            uint32_t a[4];
            a[0] = *(const uint32_t*)&Qs[qrow0 + kk];
            a[1] = *(const uint32_t*)&Qs[qrow1 + kk];
            a[2] = *(const uint32_t*)&Qs[qrow0 + kk + 8];
            a[3] = *(const uint32_t*)&Qs[qrow1 + kk + 8];
            #pragma unroll
            for (int nt = 0; nt < 8; nt++) {
                uint32_t b[2];
                b[0] = *(const uint32_t*)&Ks[(nt * 8 + g) * 72 + kk];
                b[1] = *(const uint32_t*)&Ks[(nt * 8 + g) * 72 + kk + 8];
                mma16(s[nt], a, b);
            }
        }

        // warp-local online softmax (rows g and g+8 of this warp)
        float r0 = -1e30f, r1 = -1e30f;
        #pragma unroll
        for (int nt = 0; nt < 8; nt++) {
            s[nt][0] *= 0.125f; s[nt][1] *= 0.125f;
            s[nt][2] *= 0.125f; s[nt][3] *= 0.125f;
            r0 = fmaxf(r0, fmaxf(s[nt][0], s[nt][1]));
            r1 = fmaxf(r1, fmaxf(s[nt][2], s[nt][3]));
        }
        r0 = fmaxf(r0, __shfl_xor_sync(0xffffffffu, r0, 1));
        r0 = fmaxf(r0, __shfl_xor_sync(0xffffffffu, r0, 2));
        r1 = fmaxf(r1, __shfl_xor_sync(0xffffffffu, r1, 1));
        r1 = fmaxf(r1, __shfl_xor_sync(0xffffffffu, r1, 2));

        float mn0 = fmaxf(mp0, r0), mn1 = fmaxf(mp1, r1);
        float c0 = fexp(mp0 - mn0), c1 = fexp(mp1 - mn1);
        mp0 = mn0; mp1 = mn1;

        uint32_t p0[8], p1[8];     // masked P, f16x2, rows g / g+8
        float pe0 = 0.f, pe1 = 0.f, pm0 = 0.f, pm1 = 0.f;
        #pragma unroll
        for (int nt = 0; nt < 8; nt++) {
            const int mc = kj0 + nt * 8;
            float2 mk0 = *(const float2*)&mrow0[mc];
            float2 mk1 = *(const float2*)&mrow1[mc];
            float p00 = fexp(s[nt][0] - mn0);
            float p01 = fexp(s[nt][1] - mn0);
            float p10 = fexp(s[nt][2] - mn1);
            float p11 = fexp(s[nt][3] - mn1);
            pe0 += p00 + p01; pe1 += p10 + p11;
            float q00 = p00 * mk0.x, q01 = p01 * mk0.y;
            float q10 = p10 * mk1.x, q11 = p11 * mk1.y;
            pm0 += q00 + q01; pm1 += q10 + q11;
            p0[nt] = h2pack(q00, q01);
            p1[nt] = h2pack(q10, q11);
        }
        pe0 += __shfl_xor_sync(0xffffffffu, pe0, 1);
        pe0 += __shfl_xor_sync(0xffffffffu, pe0, 2);
        pe1 += __shfl_xor_sync(0xffffffffu, pe1, 1);
        pe1 += __shfl_xor_sync(0xffffffffu, pe1, 2);
        pm0 += __shfl_xor_sync(0xffffffffu, pm0, 1);
        pm0 += __shfl_xor_sync(0xffffffffu, pm0, 2);
        pm1 += __shfl_xor_sync(0xffffffffu, pm1, 1);
        pm1 += __shfl_xor_sync(0xffffffffu, pm1, 2);
        se0 = se0 * c0 + pe0; se1 = se1 * c1 + pe1;
        sq0 = sq0 * c0 + pm0; sq1 = sq1 * c1 + pm1;
        #pragma unroll
        for (int nt = 0; nt < 8; nt++) {
            acc[nt][0] *= c0; acc[nt][1] *= c0;
            acc[nt][2] *= c1; acc[nt][3] *= c1;
        }

        // acc += P @ V : m16 x n64(dh), k = 64 keys, P from registers
        #pragma unroll
        for (int ks = 0; ks < 4; ks++) {
            uint32_t a[4];
            a[0] = p0[2 * ks];     a[1] = p1[2 * ks];
            a[2] = p0[2 * ks + 1]; a[3] = p1[2 * ks + 1];
            const int kk = ks * 16 + 2 * tg;
            #pragma unroll
            for (int nt = 0; nt < 8; nt++) {
                uint32_t b[2];
                b[0] = *(const uint32_t*)&Vs[(nt * 8 + g) * 72 + kk];
                b[1] = *(const uint32_t*)&Vs[(nt * 8 + g) * 72 + kk + 8];
                mma16(acc[nt], a, b);
            }
        }

        __syncthreads();                 // all warps done with buffer kt&1
        if (kt + 2 < L_ / 64) load_kv(kt + 2);
        cpcommit();
    }

    // epilogue: renorm, write z fp16 [token][h*64+d]
    float inv0 = 1.0f / (sq0 + 1e-10f * se0 + 1e-30f);
    float inv1 = 1.0f / (sq1 + 1e-10f * se1 + 1e-30f);
    #pragma unroll
    for (int nt = 0; nt < 8; nt++) {
        int c = hc + nt * 8 + 2 * tg;
        *(uint32_t*)&z[(tok0 + m0 + g) * D_ + c] =
            h2pack(acc[nt][0] * inv0, acc[nt][1] * inv0);
        *(uint32_t*)&z[(tok0 + m0 + g + 8) * D_ + c] =
            h2pack(acc[nt][2] * inv1, acc[nt][3] * inv1);
    }
}

// ---------------------------------------------------------------------------
extern "C" void kernel_launch(void* const* d_in, const int* in_sizes, int n_in,
                              void* d_out, int out_size)
{
    const float* x    = (const float*)d_in[0];
    const float* mask = (const float*)d_in[1];
    const float* Wqkv = (const float*)d_in[2];
    const float* Wout = (const float*)d_in[3];
    const float* bout = (const float*)d_in[4];
    float* out = (float*)d_out;

    __half *qkvh, *vt, *zh, *xh, *wqt, *wot;
    cudaGetSymbolAddress((void**)&qkvh, g_qkvh);
    cudaGetSymbolAddress((void**)&vt,   g_vt);
    cudaGetSymbolAddress((void**)&zh,   g_zh);
    cudaGetSymbolAddress((void**)&xh,   g_xh);
    cudaGetSymbolAddress((void**)&wqt,  g_wqt);
    cudaGetSymbolAddress((void**)&wot,  g_wot);

    cudaFuncSetAttribute(hgemm<true>,
                         cudaFuncAttributeMaxDynamicSharedMemorySize, HGEMM_SMEM);
    cudaFuncSetAttribute(hgemm<false>,
                         cudaFuncAttributeMaxDynamicSharedMemorySize, HGEMM_SMEM);
    cudaFuncSetAttribute(attn_mma,
                         cudaFuncAttributeMaxDynamicSharedMemorySize, ATTN_SMEM);

    // 0) operand prep: x -> fp16; W -> transposed fp16 (k-contiguous B tiles)
    f32_to_f16<<<MT_ * D_ / (256 * 8), 256>>>(x, xh);
    transpose_pack<<<dim3(N3_ / 64, D_ / 64), 256>>>(Wqkv, wqt, D_, N3_);
    transpose_pack<<<dim3(D_ / 64, D_ / 64), 256>>>(Wout, wot, D_, D_);

    // 1) QKV projection (fp16 mma, writes fp16 qkv directly)
    hgemm<true><<<dim3(N3_ / 128, MT_ / 128), 256, HGEMM_SMEM>>>(
        xh, wqt, nullptr, qkvh, MT_, N3_, D_);

    // 1b) V transposed per (b,h) for the PV mma
    v_transpose<<<dim3(32, L_ / 64), 256>>>(qkvh, vt);

    // 2) masked flash attention (fp16 mma, fp32 softmax; writes fp16 z)
    attn_mma<<<dim3(L_ / 128, B_ * H_), 256, ATTN_SMEM>>>(qkvh, vt, mask, zh);

    // 3) output projection + bias (fp16 mma, fp32 output)
    hgemm<false><<<dim3(D_ / 128, MT_ / 128), 256, HGEMM_SMEM>>>(
        zh, wot, bout, out, MT_, D_, D_);
}

// round 14
// speedup vs baseline: 3.0453x; 1.1619x over previous
#include <cuda_runtime.h>
#include <cuda_fp16.h>
#include <stdint.h>

#define B_   2
#define L_   2048
#define D_   1024
#define H_   16
#define N3_  3072
#define MT_  4096

// scratch (allocation-free rule: device globals); 16B+ aligned for uint4/cp.async
__device__ __align__(256) __half g_qkvh[(size_t)MT_ * N3_];   // fp16 qkv
__device__ __align__(256) __half g_vt[(size_t)32 * 64 * L_];  // V^T fp16
__device__ __align__(256) __half g_zh[(size_t)MT_ * D_];      // fp16 attn out
__device__ __align__(256) __half g_xh[(size_t)MT_ * D_];      // fp16 x
__device__ __align__(256) __half g_wqt[(size_t)N3_ * D_];     // W_qkv^T fp16
__device__ __align__(256) __half g_wot[(size_t)D_ * D_];      // W_out^T fp16

// pack (lo, hi) floats -> f16x2 (lo in low half)
__device__ __forceinline__ uint32_t h2pack(float lo, float hi) {
    uint32_t r; asm("cvt.rn.f16x2.f32 %0, %1, %2;" : "=r"(r) : "f"(hi), "f"(lo));
    return r;
}
__device__ __forceinline__ uint32_t hh(__half lo, __half hi) {
    __half2 t = __halves2half2(lo, hi);
    return *(uint32_t*)&t;
}

__device__ __forceinline__ void mma16(float* d, const uint32_t* a, const uint32_t* b) {
    asm volatile(
        "mma.sync.aligned.m16n8k16.row.col.f32.f16.f16.f32 "
        "{%0,%1,%2,%3}, {%4,%5,%6,%7}, {%8,%9}, {%0,%1,%2,%3};\n"
        : "+f"(d[0]), "+f"(d[1]), "+f"(d[2]), "+f"(d[3])
        : "r"(a[0]), "r"(a[1]), "r"(a[2]), "r"(a[3]), "r"(b[0]), "r"(b[1]));
}

// cp.async helpers
__device__ __forceinline__ void cpa(void* s, const void* g) {
    uint32_t sa = (uint32_t)__cvta_generic_to_shared(s);
    asm volatile("cp.async.cg.shared.global [%0], [%1], 16;\n" :: "r"(sa), "l"(g));
}
__device__ __forceinline__ void cpcommit() { asm volatile("cp.async.commit_group;\n"); }
template<int N> __device__ __forceinline__ void cpwait() {
    asm volatile("cp.async.wait_group %0;\n" :: "n"(N));
}

// ---------------------------------------------------------------------------
// fp32 -> fp16 elementwise pack (contiguous buffer, 8 elems/thread)
// ---------------------------------------------------------------------------
__global__ void f32_to_f16(const float* __restrict__ in, __half* __restrict__ out) {
    int i = (blockIdx.x * 256 + threadIdx.x) * 8;
    float4 v0 = *(const float4*)&in[i], v1 = *(const float4*)&in[i + 4];
    uint4 o;
    o.x = h2pack(v0.x, v0.y); o.y = h2pack(v0.z, v0.w);
    o.z = h2pack(v1.x, v1.y); o.w = h2pack(v1.z, v1.w);
    *(uint4*)&out[i] = o;
}

// ---------------------------------------------------------------------------
// Transpose + fp16 pack: in fp32 [K][N] -> out fp16 [N][K]. 64x64 tiles.
// ---------------------------------------------------------------------------
__global__ void transpose_pack(const float* __restrict__ in, __half* __restrict__ out,
                               int K, int N) {
    __shared__ float ts[64][68];
    const int n0 = blockIdx.x * 64, k0 = blockIdx.y * 64;
    const int tid = threadIdx.x;

    int r = tid >> 2, c0 = (tid & 3) * 16;        // ts[k][n]
    #pragma unroll
    for (int j = 0; j < 4; j++) {
        float4 v = *(const float4*)&in[(size_t)(k0 + r) * N + n0 + c0 + 4 * j];
        *(float4*)&ts[r][c0 + 4 * j] = v;
    }
    __syncthreads();

    int n = tid & 63, kk = (tid >> 6) * 16;       // 16 k per thread
    uint4 o0, o1;
    o0.x = h2pack(ts[kk +  0][n], ts[kk +  1][n]);
    o0.y = h2pack(ts[kk +  2][n], ts[kk +  3][n]);
    o0.z = h2pack(ts[kk +  4][n], ts[kk +  5][n]);
    o0.w = h2pack(ts[kk +  6][n], ts[kk +  7][n]);
    o1.x = h2pack(ts[kk +  8][n], ts[kk +  9][n]);
    o1.y = h2pack(ts[kk + 10][n], ts[kk + 11][n]);
    o1.z = h2pack(ts[kk + 12][n], ts[kk + 13][n]);
    o1.w = h2pack(ts[kk + 14][n], ts[kk + 15][n]);
    size_t orow = (size_t)(n0 + n) * K + k0 + kk;
    *(uint4*)&out[orow]     = o0;
    *(uint4*)&out[orow + 8] = o1;
}

// ---------------------------------------------------------------------------
// V transpose: qkvh V-part fp16 [token][dh] -> vt[bh][dh][token] fp16
// ---------------------------------------------------------------------------
__global__ void v_transpose(const __half* __restrict__ qkvh, __half* __restrict__ vt) {
    __shared__ __half ts[64][72];
    const int bh = blockIdx.x;             // b*16 + h
    const int t0 = blockIdx.y * 64;
    const int b = bh >> 4, hc = (bh & 15) * 64;
    const int tid = threadIdx.x;

    #pragma unroll
    for (int i = 0; i < 2; i++) {
        int id = tid + 256 * i;                  // 0..511 chunks of 8 halves
        int row = id >> 3, c = (id & 7) * 8;
        *(uint4*)&ts[row][c] =
            *(const uint4*)&qkvh[(size_t)(b * L_ + t0 + row) * N3_ + 2048 + hc + c];
    }
    __syncthreads();

    int dh = tid & 63, k0 = (tid >> 6) * 16;     // 16 tokens per thread
    uint4 o0, o1;
    o0.x = hh(ts[k0 +  0][dh], ts[k0 +  1][dh]);
    o0.y = hh(ts[k0 +  2][dh], ts[k0 +  3][dh]);
    o0.z = hh(ts[k0 +  4][dh], ts[k0 +  5][dh]);
    o0.w = hh(ts[k0 +  6][dh], ts[k0 +  7][dh]);
    o1.x = hh(ts[k0 +  8][dh], ts[k0 +  9][dh]);
    o1.y = hh(ts[k0 + 10][dh], ts[k0 + 11][dh]);
    o1.z = hh(ts[k0 + 12][dh], ts[k0 + 13][dh]);
    o1.w = hh(ts[k0 + 14][dh], ts[k0 + 15][dh]);
    size_t vrow = ((size_t)bh * 64 + dh) * L_ + t0 + k0;
    *(uint4*)&vt[vrow]     = o0;
    *(uint4*)&vt[vrow + 8] = o1;
}

// ---------------------------------------------------------------------------
// fp16 mma GEMM: C[M,N] = A[M,K] @ Bt[N,K]^T, fp32 accum.
// 128x128 tile, K-chunk 64 (64 mmas/barrier), 2-stage cp.async, 8 warps.
// smem stride 72 halves: frag bank = (36g+tg)%32 — bijective, conflict-free.
// ---------------------------------------------------------------------------
#define HKC 64
#define H_ST 72
#define HSTG (256 * H_ST)                 // halves per stage (A128 + B128 rows)
#define HGEMM_SMEM (2 * HSTG * 2)         // 73728 bytes

template<bool OUTF16>
__global__ __launch_bounds__(256, 2)
void hgemm(const __half* __restrict__ A, const __half* __restrict__ Bt,
           const float* __restrict__ bias, void* __restrict__ Cout,
           int M, int N, int K)
{
    extern __shared__ __half hsm[];
    const int tid  = threadIdx.x;
    const int w    = tid >> 5, lane = tid & 31;
    const int g    = lane >> 2, tg = lane & 3;
    const int wm   = (w >> 2) * 64;
    const int wn   = (w & 3) * 32;
    const int row0 = blockIdx.y * 128, col0 = blockIdx.x * 128;

    float acc[16][4];
    #pragma unroll
    for (int i = 0; i < 16; i++)
        #pragma unroll
        for (int j = 0; j < 4; j++) acc[i][j] = 0.f;

    const int nIter = K / HKC;

    auto load_stage = [&](int it) {
        const int k0 = it * HKC;
        __half* as = hsm + (it & 1) * HSTG;
        __half* bs = as + 128 * H_ST;
        #pragma unroll
        for (int i = 0; i < 4; i++) {
            int id = tid + 256 * i;               // 1024 chunks of 8 halves
            int r = id >> 3, c = (id & 7) * 8;    // 128 rows x 64 halves
            cpa(&as[r * H_ST + c], &A[(size_t)(row0 + r) * K + k0 + c]);
            cpa(&bs[r * H_ST + c], &Bt[(size_t)(col0 + r) * K + k0 + c]);
        }
    };

    load_stage(0); cpcommit();

    for (int it = 0; it < nIter; it++) {
        if (it + 1 < nIter) load_stage(it + 1);
        cpcommit();
        cpwait<1>();
        __syncthreads();

        const __half* as = hsm + (it & 1) * HSTG;
        const __half* bs = as + 128 * H_ST;
        #pragma unroll
        for (int ks = 0; ks < 4; ks++) {
            const int kk = ks * 16 + 2 * tg;
            uint32_t a[4][4], b[4][2];
            #pragma unroll
            for (int mt = 0; mt < 4; mt++) {
                const int m = wm + mt * 16;
                a[mt][0] = *(const uint32_t*)&as[(m + g    ) * H_ST + kk];
                a[mt][1] = *(const uint32_t*)&as[(m + g + 8) * H_ST + kk];
                a[mt][2] = *(const uint32_t*)&as[(m + g    ) * H_ST + kk + 8];
                a[mt][3] = *(const uint32_t*)&as[(m + g + 8) * H_ST + kk + 8];
            }
            #pragma unroll
            for (int nt = 0; nt < 4; nt++) {
                const int n = wn + nt * 8;
                b[nt][0] = *(const uint32_t*)&bs[(n + g) * H_ST + kk];
                b[nt][1] = *(const uint32_t*)&bs[(n + g) * H_ST + kk + 8];
            }
            #pragma unroll
            for (int mt = 0; mt < 4; mt++)
                #pragma unroll
                for (int nt = 0; nt < 4; nt++)
                    mma16(acc[mt * 4 + nt], a[mt], b[nt]);
        }
        __syncthreads();
    }

    #pragma unroll
    for (int mt = 0; mt < 4; mt++) {
        #pragma unroll
        for (int nt = 0; nt < 4; nt++) {
            int r = row0 + wm + mt * 16 + g;
            int c = col0 + wn + nt * 8 + 2 * tg;
            float v0 = acc[mt * 4 + nt][0], v1 = acc[mt * 4 + nt][1];
            float v2 = acc[mt * 4 + nt][2], v3 = acc[mt * 4 + nt][3];
            if (OUTF16) {
                __half* C = (__half*)Cout;
                *(uint32_t*)&C[(size_t)r * N + c]       = h2pack(v0, v1);
                *(uint32_t*)&C[(size_t)(r + 8) * N + c] = h2pack(v2, v3);
            } else {
                float* C = (float*)Cout;
                float b0 = bias[c], b1 = bias[c + 1];
                *(float2*)&C[(size_t)r * N + c]       = make_float2(v0 + b0, v1 + b1);
                *(float2*)&C[(size_t)(r + 8) * N + c] = make_float2(v2 + b0, v3 + b1);
            }
        }
    }
}

// ---------------------------------------------------------------------------
// Flash attention, fp16 mma, fp32 softmax; MUFU exp (__expf) — softmax off the
// FMA pipe; 3-buffer K/V^T cp.async ring -> ONE barrier per iteration.
//   out = sum(e^{s-m}*mask*v) / (sum(e^{s-m}*mask) + eps*sum(e^{s-m}))
// Block: 128 q-rows x one (b,h); warp owns 16 q-rows (softmax warp-local).
// P register-resident. smem stride 72 halves (conflict-free frags).
// ---------------------------------------------------------------------------
#define QS_B 0                            // Qs: 128*72*2 = 18432 B
#define KS_B 18432                        // Ks: 3 x 64*72*2 = 27648 B
#define VT_B (18432 + 27648)              // Vt: 3 x 64*72*2
#define ATTN_SMEM (VT_B + 27648)          // 73728 B total (2 CTAs/SM ok)

__global__ __launch_bounds__(256)
void attn_mma(const __half* __restrict__ qkvh,
              const __half* __restrict__ vtg,
              const float* __restrict__ mask, __half* __restrict__ z)
{
    extern __shared__ char smc[];
    __half* Qs = (__half*)(smc + QS_B);

    const int tid = threadIdx.x;
    const int w = tid >> 5, lane = tid & 31;
    const int g = lane >> 2, tg = lane & 3;
    const int m0 = w * 16;
    const int bb = blockIdx.y >> 4;
    const int h  = blockIdx.y & 15;
    const int qi0 = blockIdx.x * 128;
    const size_t tok0 = (size_t)bb * L_ + qi0;
    const int hc = h * 64;

    auto load_kv = [&](int kt) {
        __half* ks = (__half*)(smc + KS_B + (kt % 3) * 9216);
        __half* vs = (__half*)(smc + VT_B + (kt % 3) * 9216);
        int r = tid >> 2, c0 = (tid & 3) * 16;
        const size_t ktok = (size_t)bb * L_ + kt * 64;
        cpa(&ks[r * 72 + c0],     &qkvh[(ktok + r) * N3_ + 1024 + hc + c0]);
        cpa(&ks[r * 72 + c0 + 8], &qkvh[(ktok + r) * N3_ + 1024 + hc + c0 + 8]);
        const size_t vrow = ((size_t)(bb * 16 + h) * 64 + r) * L_ + kt * 64;
        cpa(&vs[r * 72 + c0],     &vtg[vrow + c0]);
        cpa(&vs[r * 72 + c0 + 8], &vtg[vrow + c0 + 8]);
    };

    // prologue: group0 = Q + K/V(0); group1 = K/V(1)
    {
        int r = tid >> 1, c0 = (tid & 1) * 32;
        #pragma unroll
        for (int j = 0; j < 4; j++)
            cpa(&Qs[r * 72 + c0 + 8 * j], &qkvh[(tok0 + r) * N3_ + hc + c0 + 8 * j]);
    }
    load_kv(0); cpcommit();
    load_kv(1); cpcommit();

    float acc[8][4];
    #pragma unroll
    for (int i = 0; i < 8; i++)
        #pragma unroll
        for (int j = 0; j < 4; j++) acc[i][j] = 0.f;
    float mp0 = -1e30f, mp1 = -1e30f;
    float se0 = 0.f, se1 = 0.f, sq0 = 0.f, sq1 = 0.f;

    const float* mrow0 = mask + (tok0 + m0 + g) * L_ + 2 * tg;
    const float* mrow1 = mrow0 + 8 * (size_t)L_;
    const int qrow0 = (m0 + g) * 72, qrow1 = (m0 + g + 8) * 72;

    for (int kt = 0; kt < L_ / 64; kt++) {
        const int kj0 = kt * 64;
        cpwait<1>();                     // group kt complete
        __syncthreads();                 // and all warps done with buffer (kt+2)%3
        if (kt + 2 < L_ / 64) load_kv(kt + 2);
        cpcommit();

        const __half* Ks = (const __half*)(smc + KS_B + (kt % 3) * 9216);
        const __half* Vs = (const __half*)(smc + VT_B + (kt % 3) * 9216);

        // S = Q @ K^T : m16 x n64, fp16 k16 x 4 steps
        float s[8][4];
        #pragma unroll
        for (int nt = 0; nt < 8; nt++)
            #pragma unroll
            for (int j = 0; j < 4; j++) s[nt][j] = 0.f;
        #pragma unroll
        for (int ks = 0; ks < 4; ks++) {
            const int kk = ks * 16 + 2 * tg;
            uint32_t a[4];
            a[0] = *(const uint32_t*)&Qs[qrow0 + kk];
            a[1] = *(const uint32_t*)&Qs[qrow1 + kk];
            a[2] = *(const uint32_t*)&Qs[qrow0 + kk + 8];
            a[3] = *(const uint32_t*)&Qs[qrow1 + kk + 8];
            #pragma unroll
            for (int nt = 0; nt < 8; nt++) {
                uint32_t b[2];
                b[0] = *(const uint32_t*)&Ks[(nt * 8 + g) * 72 + kk];
                b[1] = *(const uint32_t*)&Ks[(nt * 8 + g) * 72 + kk + 8];
                mma16(s[nt], a, b);
            }
        }

        // warp-local online softmax (rows g and g+8 of this warp)
        float r0 = -1e30f, r1 = -1e30f;
        #pragma unroll
        for (int nt = 0; nt < 8; nt++) {
            s[nt][0] *= 0.125f; s[nt][1] *= 0.125f;
            s[nt][2] *= 0.125f; s[nt][3] *= 0.125f;
            r0 = fmaxf(r0, fmaxf(s[nt][0], s[nt][1]));
            r1 = fmaxf(r1, fmaxf(s[nt][2], s[nt][3]));
        }
        r0 = fmaxf(r0, __shfl_xor_sync(0xffffffffu, r0, 1));
        r0 = fmaxf(r0, __shfl_xor_sync(0xffffffffu, r0, 2));
        r1 = fmaxf(r1, __shfl_xor_sync(0xffffffffu, r1, 1));
        r1 = fmaxf(r1, __shfl_xor_sync(0xffffffffu, r1, 2));

        float mn0 = fmaxf(mp0, r0), mn1 = fmaxf(mp1, r1);
        float c0 = __expf(mp0 - mn0), c1 = __expf(mp1 - mn1);
        mp0 = mn0; mp1 = mn1;

        uint32_t p0[8], p1[8];     // masked P, f16x2, rows g / g+8
        float pe0 = 0.f, pe1 = 0.f, pm0 = 0.f, pm1 = 0.f;
        #pragma unroll
        for (int nt = 0; nt < 8; nt++) {
            const int mc = kj0 + nt * 8;
            float2 mk0 = *(const float2*)&mrow0[mc];
            float2 mk1 = *(const float2*)&mrow1[mc];
            float p00 = __expf(s[nt][0] - mn0);
            float p01 = __expf(s[nt][1] - mn0);
            float p10 = __expf(s[nt][2] - mn1);
            float p11 = __expf(s[nt][3] - mn1);
            pe0 += p00 + p01; pe1 += p10 + p11;
            float q00 = p00 * mk0.x, q01 = p01 * mk0.y;
            float q10 = p10 * mk1.x, q11 = p11 * mk1.y;
            pm0 += q00 + q01; pm1 += q10 + q11;
            p0[nt] = h2pack(q00, q01);
            p1[nt] = h2pack(q10, q11);
        }
        pe0 += __shfl_xor_sync(0xffffffffu, pe0, 1);
        pe0 += __shfl_xor_sync(0xffffffffu, pe0, 2);
        pe1 += __shfl_xor_sync(0xffffffffu, pe1, 1);
        pe1 += __shfl_xor_sync(0xffffffffu, pe1, 2);
        pm0 += __shfl_xor_sync(0xffffffffu, pm0, 1);
        pm0 += __shfl_xor_sync(0xffffffffu, pm0, 2);
        pm1 += __shfl_xor_sync(0xffffffffu, pm1, 1);
        pm1 += __shfl_xor_sync(0xffffffffu, pm1, 2);
        se0 = se0 * c0 + pe0; se1 = se1 * c1 + pe1;
        sq0 = sq0 * c0 + pm0; sq1 = sq1 * c1 + pm1;
        #pragma unroll
        for (int nt = 0; nt < 8; nt++) {
            acc[nt][0] *= c0; acc[nt][1] *= c0;
            acc[nt][2] *= c1; acc[nt][3] *= c1;
        }

        // acc += P @ V : m16 x n64(dh), k = 64 keys, P from registers
        #pragma unroll
        for (int ks = 0; ks < 4; ks++) {
            uint32_t a[4];
            a[0] = p0[2 * ks];     a[1] = p1[2 * ks];
            a[2] = p0[2 * ks + 1]; a[3] = p1[2 * ks + 1];
            const int kk = ks * 16 + 2 * tg;
            #pragma unroll
            for (int nt = 0; nt < 8; nt++) {
                uint32_t b[2];
                b[0] = *(const uint32_t*)&Vs[(nt * 8 + g) * 72 + kk];
                b[1] = *(const uint32_t*)&Vs[(nt * 8 + g) * 72 + kk + 8];
                mma16(acc[nt], a, b);
            }
        }
    }

    // epilogue: renorm, write z fp16 [token][h*64+d]
    float inv0 = 1.0f / (sq0 + 1e-10f * se0 + 1e-30f);
    float inv1 = 1.0f / (sq1 + 1e-10f * se1 + 1e-30f);
    #pragma unroll
    for (int nt = 0; nt < 8; nt++) {
        int c = hc + nt * 8 + 2 * tg;
        *(uint32_t*)&z[(tok0 + m0 + g) * D_ + c] =
            h2pack(acc[nt][0] * inv0, acc[nt][1] * inv0);
        *(uint32_t*)&z[(tok0 + m0 + g + 8) * D_ + c] =
            h2pack(acc[nt][2] * inv1, acc[nt][3] * inv1);
    }
}

// ---------------------------------------------------------------------------
extern "C" void kernel_launch(void* const* d_in, const int* in_sizes, int n_in,
                              void* d_out, int out_size)
{
    const float* x    = (const float*)d_in[0];
    const float* mask = (const float*)d_in[1];
    const float* Wqkv = (const float*)d_in[2];
    const float* Wout = (const float*)d_in[3];
    const float* bout = (const float*)d_in[4];
    float* out = (float*)d_out;

    __half *qkvh, *vt, *zh, *xh, *wqt, *wot;
    cudaGetSymbolAddress((void**)&qkvh, g_qkvh);
    cudaGetSymbolAddress((void**)&vt,   g_vt);
    cudaGetSymbolAddress((void**)&zh,   g_zh);
    cudaGetSymbolAddress((void**)&xh,   g_xh);
    cudaGetSymbolAddress((void**)&wqt,  g_wqt);
    cudaGetSymbolAddress((void**)&wot,  g_wot);

    cudaFuncSetAttribute(hgemm<true>,
                         cudaFuncAttributeMaxDynamicSharedMemorySize, HGEMM_SMEM);
    cudaFuncSetAttribute(hgemm<false>,
                         cudaFuncAttributeMaxDynamicSharedMemorySize, HGEMM_SMEM);
    cudaFuncSetAttribute(attn_mma,
                         cudaFuncAttributeMaxDynamicSharedMemorySize, ATTN_SMEM);

    // 0) operand prep: x -> fp16; W -> transposed fp16 (k-contiguous B tiles)
    f32_to_f16<<<MT_ * D_ / (256 * 8), 256>>>(x, xh);
    transpose_pack<<<dim3(N3_ / 64, D_ / 64), 256>>>(Wqkv, wqt, D_, N3_);
    transpose_pack<<<dim3(D_ / 64, D_ / 64), 256>>>(Wout, wot, D_, D_);

    // 1) QKV projection (fp16 mma, writes fp16 qkv directly)
    hgemm<true><<<dim3(N3_ / 128, MT_ / 128), 256, HGEMM_SMEM>>>(
        xh, wqt, nullptr, qkvh, MT_, N3_, D_);

    // 1b) V transposed per (b,h) for the PV mma
    v_transpose<<<dim3(32, L_ / 64), 256>>>(qkvh, vt);

    // 2) masked flash attention (fp16 mma, fp32 softmax; writes fp16 z)
    attn_mma<<<dim3(L_ / 128, B_ * H_), 256, ATTN_SMEM>>>(qkvh, vt, mask, zh);

    // 3) output projection + bias (fp16 mma, fp32 output)
    hgemm<false><<<dim3(D_ / 128, MT_ / 128), 256, HGEMM_SMEM>>>(
        zh, wot, bout, out, MT_, D_, D_);
}

// round 15
// speedup vs baseline: 3.1418x; 1.0317x over previous
#include <cuda_runtime.h>
#include <cuda_fp16.h>
#include <stdint.h>

#define B_   2
#define L_   2048
#define D_   1024
#define H_   16
#define N3_  3072
#define MT_  4096

// scratch (allocation-free rule: device globals); 16B+ aligned for uint4/cp.async
__device__ __align__(256) __half g_qkvh[(size_t)MT_ * N3_];   // fp16 qkv (Q pre-scaled)
__device__ __align__(256) __half g_vt[(size_t)32 * 64 * L_];  // V^T fp16
__device__ __align__(256) __half g_zh[(size_t)MT_ * D_];      // fp16 attn out
__device__ __align__(256) __half g_xh[(size_t)MT_ * D_];      // fp16 x
__device__ __align__(256) __half g_wqt[(size_t)N3_ * D_];     // W_qkv^T fp16
__device__ __align__(256) __half g_wot[(size_t)D_ * D_];      // W_out^T fp16

// pack (lo, hi) floats -> f16x2 (lo in low half)
__device__ __forceinline__ uint32_t h2pack(float lo, float hi) {
    uint32_t r; asm("cvt.rn.f16x2.f32 %0, %1, %2;" : "=r"(r) : "f"(hi), "f"(lo));
    return r;
}
__device__ __forceinline__ uint32_t hh(__half lo, __half hi) {
    __half2 t = __halves2half2(lo, hi);
    return *(uint32_t*)&t;
}

__device__ __forceinline__ void mma16(float* d, const uint32_t* a, const uint32_t* b) {
    asm volatile(
        "mma.sync.aligned.m16n8k16.row.col.f32.f16.f16.f32 "
        "{%0,%1,%2,%3}, {%4,%5,%6,%7}, {%8,%9}, {%0,%1,%2,%3};\n"
        : "+f"(d[0]), "+f"(d[1]), "+f"(d[2]), "+f"(d[3])
        : "r"(a[0]), "r"(a[1]), "r"(a[2]), "r"(a[3]), "r"(b[0]), "r"(b[1]));
}

// cp.async helpers
__device__ __forceinline__ void cpa(void* s, const void* g) {
    uint32_t sa = (uint32_t)__cvta_generic_to_shared(s);
    asm volatile("cp.async.cg.shared.global [%0], [%1], 16;\n" :: "r"(sa), "l"(g));
}
__device__ __forceinline__ void cpcommit() { asm volatile("cp.async.commit_group;\n"); }
template<int N> __device__ __forceinline__ void cpwait() {
    asm volatile("cp.async.wait_group %0;\n" :: "n"(N));
}

// ---------------------------------------------------------------------------
// fp32 -> fp16 elementwise pack (contiguous buffer, 8 elems/thread)
// ---------------------------------------------------------------------------
__global__ void f32_to_f16(const float* __restrict__ in, __half* __restrict__ out) {
    int i = (blockIdx.x * 256 + threadIdx.x) * 8;
    float4 v0 = *(const float4*)&in[i], v1 = *(const float4*)&in[i + 4];
    uint4 o;
    o.x = h2pack(v0.x, v0.y); o.y = h2pack(v0.z, v0.w);
    o.z = h2pack(v1.x, v1.y); o.w = h2pack(v1.z, v1.w);
    *(uint4*)&out[i] = o;
}

// ---------------------------------------------------------------------------
// Transpose + fp16 pack: in fp32 [K][N] -> out fp16 [N][K]. 64x64 tiles.
// ---------------------------------------------------------------------------
__global__ void transpose_pack(const float* __restrict__ in, __half* __restrict__ out,
                               int K, int N) {
    __shared__ float ts[64][68];
    const int n0 = blockIdx.x * 64, k0 = blockIdx.y * 64;
    const int tid = threadIdx.x;

    int r = tid >> 2, c0 = (tid & 3) * 16;        // ts[k][n]
    #pragma unroll
    for (int j = 0; j < 4; j++) {
        float4 v = *(const float4*)&in[(size_t)(k0 + r) * N + n0 + c0 + 4 * j];
        *(float4*)&ts[r][c0 + 4 * j] = v;
    }
    __syncthreads();

    int n = tid & 63, kk = (tid >> 6) * 16;       // 16 k per thread
    uint4 o0, o1;
    o0.x = h2pack(ts[kk +  0][n], ts[kk +  1][n]);
    o0.y = h2pack(ts[kk +  2][n], ts[kk +  3][n]);
    o0.z = h2pack(ts[kk +  4][n], ts[kk +  5][n]);
    o0.w = h2pack(ts[kk +  6][n], ts[kk +  7][n]);
    o1.x = h2pack(ts[kk +  8][n], ts[kk +  9][n]);
    o1.y = h2pack(ts[kk + 10][n], ts[kk + 11][n]);
    o1.z = h2pack(ts[kk + 12][n], ts[kk + 13][n]);
    o1.w = h2pack(ts[kk + 14][n], ts[kk + 15][n]);
    size_t orow = (size_t)(n0 + n) * K + k0 + kk;
    *(uint4*)&out[orow]     = o0;
    *(uint4*)&out[orow + 8] = o1;
}

// ---------------------------------------------------------------------------
// V transpose: qkvh V-part fp16 [token][dh] -> vt[bh][dh][token] fp16
// ---------------------------------------------------------------------------
__global__ void v_transpose(const __half* __restrict__ qkvh, __half* __restrict__ vt) {
    __shared__ __half ts[64][72];
    const int bh = blockIdx.x;             // b*16 + h
    const int t0 = blockIdx.y * 64;
    const int b = bh >> 4, hc = (bh & 15) * 64;
    const int tid = threadIdx.x;

    #pragma unroll
    for (int i = 0; i < 2; i++) {
        int id = tid + 256 * i;                  // 0..511 chunks of 8 halves
        int row = id >> 3, c = (id & 7) * 8;
        *(uint4*)&ts[row][c] =
            *(const uint4*)&qkvh[(size_t)(b * L_ + t0 + row) * N3_ + 2048 + hc + c];
    }
    __syncthreads();

    int dh = tid & 63, k0 = (tid >> 6) * 16;     // 16 tokens per thread
    uint4 o0, o1;
    o0.x = hh(ts[k0 +  0][dh], ts[k0 +  1][dh]);
    o0.y = hh(ts[k0 +  2][dh], ts[k0 +  3][dh]);
    o0.z = hh(ts[k0 +  4][dh], ts[k0 +  5][dh]);
    o0.w = hh(ts[k0 +  6][dh], ts[k0 +  7][dh]);
    o1.x = hh(ts[k0 +  8][dh], ts[k0 +  9][dh]);
    o1.y = hh(ts[k0 + 10][dh], ts[k0 + 11][dh]);
    o1.z = hh(ts[k0 + 12][dh], ts[k0 + 13][dh]);
    o1.w = hh(ts[k0 + 14][dh], ts[k0 + 15][dh]);
    size_t vrow = ((size_t)bh * 64 + dh) * L_ + t0 + k0;
    *(uint4*)&vt[vrow]     = o0;
    *(uint4*)&vt[vrow + 8] = o1;
}

// ---------------------------------------------------------------------------
// fp16 mma GEMM: C[M,N] = A[M,K] @ Bt[N,K]^T, fp32 accum.
// 128x128 tile, K-chunk 64, 2-stage cp.async, 8 warps 2(m)x4(n).
// smem stride 72 halves: frag bank = (36g+tg)%32 — bijective, conflict-free.
// OUTF16: write fp16, scaling columns < D_ by 0.125 (Q pre-scale for
// attention; exact — power of two). else: +bias, fp32 out.
// ---------------------------------------------------------------------------
#define HKC 64
#define H_ST 72
#define HSTG (256 * H_ST)                 // halves per stage (A128 + B128 rows)
#define HGEMM_SMEM (2 * HSTG * 2)         // 73728 bytes

template<bool OUTF16>
__global__ __launch_bounds__(256, 2)
void hgemm(const __half* __restrict__ A, const __half* __restrict__ Bt,
           const float* __restrict__ bias, void* __restrict__ Cout,
           int M, int N, int K)
{
    extern __shared__ __half hsm[];
    const int tid  = threadIdx.x;
    const int w    = tid >> 5, lane = tid & 31;
    const int g    = lane >> 2, tg = lane & 3;
    const int wm   = (w >> 2) * 64;
    const int wn   = (w & 3) * 32;
    const int row0 = blockIdx.y * 128, col0 = blockIdx.x * 128;

    float acc[16][4];
    #pragma unroll
    for (int i = 0; i < 16; i++)
        #pragma unroll
        for (int j = 0; j < 4; j++) acc[i][j] = 0.f;

    const int nIter = K / HKC;

    auto load_stage = [&](int it) {
        const int k0 = it * HKC;
        __half* as = hsm + (it & 1) * HSTG;
        __half* bs = as + 128 * H_ST;
        #pragma unroll
        for (int i = 0; i < 4; i++) {
            int id = tid + 256 * i;               // 1024 chunks of 8 halves
            int r = id >> 3, c = (id & 7) * 8;    // 128 rows x 64 halves
            cpa(&as[r * H_ST + c], &A[(size_t)(row0 + r) * K + k0 + c]);
            cpa(&bs[r * H_ST + c], &Bt[(size_t)(col0 + r) * K + k0 + c]);
        }
    };

    load_stage(0); cpcommit();

    for (int it = 0; it < nIter; it++) {
        if (it + 1 < nIter) load_stage(it + 1);
        cpcommit();
        cpwait<1>();
        __syncthreads();

        const __half* as = hsm + (it & 1) * HSTG;
        const __half* bs = as + 128 * H_ST;
        #pragma unroll
        for (int ks = 0; ks < 4; ks++) {
            const int kk = ks * 16 + 2 * tg;
            uint32_t a[4][4], b[4][2];
            #pragma unroll
            for (int mt = 0; mt < 4; mt++) {
                const int m = wm + mt * 16;
                a[mt][0] = *(const uint32_t*)&as[(m + g    ) * H_ST + kk];
                a[mt][1] = *(const uint32_t*)&as[(m + g + 8) * H_ST + kk];
                a[mt][2] = *(const uint32_t*)&as[(m + g    ) * H_ST + kk + 8];
                a[mt][3] = *(const uint32_t*)&as[(m + g + 8) * H_ST + kk + 8];
            }
            #pragma unroll
            for (int nt = 0; nt < 4; nt++) {
                const int n = wn + nt * 8;
                b[nt][0] = *(const uint32_t*)&bs[(n + g) * H_ST + kk];
                b[nt][1] = *(const uint32_t*)&bs[(n + g) * H_ST + kk + 8];
            }
            #pragma unroll
            for (int mt = 0; mt < 4; mt++)
                #pragma unroll
                for (int nt = 0; nt < 4; nt++)
                    mma16(acc[mt * 4 + nt], a[mt], b[nt]);
        }
        __syncthreads();
    }

    #pragma unroll
    for (int mt = 0; mt < 4; mt++) {
        #pragma unroll
        for (int nt = 0; nt < 4; nt++) {
            int r = row0 + wm + mt * 16 + g;
            int c = col0 + wn + nt * 8 + 2 * tg;
            float v0 = acc[mt * 4 + nt][0], v1 = acc[mt * 4 + nt][1];
            float v2 = acc[mt * 4 + nt][2], v3 = acc[mt * 4 + nt][3];
            if (OUTF16) {
                // Q columns pre-scaled by softmax 1/sqrt(dh) = 0.125 (exact)
                float sc = (c < D_) ? 0.125f : 1.0f;
                __half* C = (__half*)Cout;
                *(uint32_t*)&C[(size_t)r * N + c]       = h2pack(v0 * sc, v1 * sc);
                *(uint32_t*)&C[(size_t)(r + 8) * N + c] = h2pack(v2 * sc, v3 * sc);
            } else {
                float* C = (float*)Cout;
                float b0 = bias[c], b1 = bias[c + 1];
                *(float2*)&C[(size_t)r * N + c]       = make_float2(v0 + b0, v1 + b1);
                *(float2*)&C[(size_t)(r + 8) * N + c] = make_float2(v2 + b0, v3 + b1);
            }
        }
    }
}

// ---------------------------------------------------------------------------
// Flash attention, fp16 mma, fp32 softmax (MUFU exp), 3-buffer K/V ring,
// ONE barrier per iteration, mask prefetched to REGISTERS at iteration top
// (hides its DRAM latency under the S-mma). Q pre-scaled by 0.125 upstream.
//   out = sum(e^{s-m}*mask*v) / (sum(e^{s-m}*mask) + eps*sum(e^{s-m}))
// launch_bounds(256,2) pins regs <= 128 so occupancy stays 2 CTA/SM.
// ---------------------------------------------------------------------------
#define QS_B 0                            // Qs: 128*72*2 = 18432 B
#define KS_B 18432                        // Ks: 3 x 64*72*2 = 27648 B
#define VT_B (18432 + 27648)              // Vt: 3 x 64*72*2
#define ATTN_SMEM (VT_B + 27648)          // 73728 B total

__global__ __launch_bounds__(256, 2)
void attn_mma(const __half* __restrict__ qkvh,
              const __half* __restrict__ vtg,
              const float* __restrict__ mask, __half* __restrict__ z)
{
    extern __shared__ char smc[];
    __half* Qs = (__half*)(smc + QS_B);

    const int tid = threadIdx.x;
    const int w = tid >> 5, lane = tid & 31;
    const int g = lane >> 2, tg = lane & 3;
    const int m0 = w * 16;
    const int bb = blockIdx.y >> 4;
    const int h  = blockIdx.y & 15;
    const int qi0 = blockIdx.x * 128;
    const size_t tok0 = (size_t)bb * L_ + qi0;
    const int hc = h * 64;

    auto load_kv = [&](int kt) {
        __half* ks = (__half*)(smc + KS_B + (kt % 3) * 9216);
        __half* vs = (__half*)(smc + VT_B + (kt % 3) * 9216);
        int r = tid >> 2, c0 = (tid & 3) * 16;
        const size_t ktok = (size_t)bb * L_ + kt * 64;
        cpa(&ks[r * 72 + c0],     &qkvh[(ktok + r) * N3_ + 1024 + hc + c0]);
        cpa(&ks[r * 72 + c0 + 8], &qkvh[(ktok + r) * N3_ + 1024 + hc + c0 + 8]);
        const size_t vrow = ((size_t)(bb * 16 + h) * 64 + r) * L_ + kt * 64;
        cpa(&vs[r * 72 + c0],     &vtg[vrow + c0]);
        cpa(&vs[r * 72 + c0 + 8], &vtg[vrow + c0 + 8]);
    };

    // prologue: group0 = Q + K/V(0); group1 = K/V(1)
    {
        int r = tid >> 1, c0 = (tid & 1) * 32;
        #pragma unroll
        for (int j = 0; j < 4; j++)
            cpa(&Qs[r * 72 + c0 + 8 * j], &qkvh[(tok0 + r) * N3_ + hc + c0 + 8 * j]);
    }
    load_kv(0); cpcommit();
    load_kv(1); cpcommit();

    float acc[8][4];
    #pragma unroll
    for (int i = 0; i < 8; i++)
        #pragma unroll
        for (int j = 0; j < 4; j++) acc[i][j] = 0.f;
    float mp0 = -1e30f, mp1 = -1e30f;
    float se0 = 0.f, se1 = 0.f, sq0 = 0.f, sq1 = 0.f;

    const float* mrow0 = mask + (tok0 + m0 + g) * L_ + 2 * tg;
    const float* mrow1 = mrow0 + 8 * (size_t)L_;
    const int qrow0 = (m0 + g) * 72, qrow1 = (m0 + g + 8) * 72;

    for (int kt = 0; kt < L_ / 64; kt++) {
        const int kj0 = kt * 64;
        cpwait<1>();                     // group kt complete
        __syncthreads();                 // all warps done with buffer (kt+2)%3
        if (kt + 2 < L_ / 64) load_kv(kt + 2);
        cpcommit();

        // prefetch mask tile into registers — consumed AFTER the S-mma,
        // so ~1500 cycles of tensor work cover the DRAM latency.
        float2 mk0[8], mk1[8];
        #pragma unroll
        for (int nt = 0; nt < 8; nt++) {
            mk0[nt] = *(const float2*)&mrow0[kj0 + nt * 8];
            mk1[nt] = *(const float2*)&mrow1[kj0 + nt * 8];
        }

        const __half* Ks = (const __half*)(smc + KS_B + (kt % 3) * 9216);
        const __half* Vs = (const __half*)(smc + VT_B + (kt % 3) * 9216);

        // S = (Q/8) @ K^T : m16 x n64, fp16 k16 x 4 steps
        float s[8][4];
        #pragma unroll
        for (int nt = 0; nt < 8; nt++)
            #pragma unroll
            for (int j = 0; j < 4; j++) s[nt][j] = 0.f;
        #pragma unroll
        for (int ks = 0; ks < 4; ks++) {
            const int kk = ks * 16 + 2 * tg;
            uint32_t a[4];
            a[0] = *(const uint32_t*)&Qs[qrow0 + kk];
            a[1] = *(const uint32_t*)&Qs[qrow1 + kk];
            a[2] = *(const uint32_t*)&Qs[qrow0 + kk + 8];
            a[3] = *(const uint32_t*)&Qs[qrow1 + kk + 8];
            #pragma unroll
            for (int nt = 0; nt < 8; nt++) {
                uint32_t b[2];
                b[0] = *(const uint32_t*)&Ks[(nt * 8 + g) * 72 + kk];
                b[1] = *(const uint32_t*)&Ks[(nt * 8 + g) * 72 + kk + 8];
                mma16(s[nt], a, b);
            }
        }

        // warp-local online softmax (rows g and g+8; scores pre-scaled)
        float r0 = -1e30f, r1 = -1e30f;
        #pragma unroll
        for (int nt = 0; nt < 8; nt++) {
            r0 = fmaxf(r0, fmaxf(s[nt][0], s[nt][1]));
            r1 = fmaxf(r1, fmaxf(s[nt][2], s[nt][3]));
        }
        r0 = fmaxf(r0, __shfl_xor_sync(0xffffffffu, r0, 1));
        r0 = fmaxf(r0, __shfl_xor_sync(0xffffffffu, r0, 2));
        r1 = fmaxf(r1, __shfl_xor_sync(0xffffffffu, r1, 1));
        r1 = fmaxf(r1, __shfl_xor_sync(0xffffffffu, r1, 2));

        float mn0 = fmaxf(mp0, r0), mn1 = fmaxf(mp1, r1);
        float c0 = __expf(mp0 - mn0), c1 = __expf(mp1 - mn1);
        mp0 = mn0; mp1 = mn1;

        uint32_t p0[8], p1[8];     // masked P, f16x2, rows g / g+8
        float pe0 = 0.f, pe1 = 0.f, pm0 = 0.f, pm1 = 0.f;
        #pragma unroll
        for (int nt = 0; nt < 8; nt++) {
            float p00 = __expf(s[nt][0] - mn0);
            float p01 = __expf(s[nt][1] - mn0);
            float p10 = __expf(s[nt][2] - mn1);
            float p11 = __expf(s[nt][3] - mn1);
            pe0 += p00 + p01; pe1 += p10 + p11;
            float q00 = p00 * mk0[nt].x, q01 = p01 * mk0[nt].y;
            float q10 = p10 * mk1[nt].x, q11 = p11 * mk1[nt].y;
            pm0 += q00 + q01; pm1 += q10 + q11;
            p0[nt] = h2pack(q00, q01);
            p1[nt] = h2pack(q10, q11);
        }
        pe0 += __shfl_xor_sync(0xffffffffu, pe0, 1);
        pe0 += __shfl_xor_sync(0xffffffffu, pe0, 2);
        pe1 += __shfl_xor_sync(0xffffffffu, pe1, 1);
        pe1 += __shfl_xor_sync(0xffffffffu, pe1, 2);
        pm0 += __shfl_xor_sync(0xffffffffu, pm0, 1);
        pm0 += __shfl_xor_sync(0xffffffffu, pm0, 2);
        pm1 += __shfl_xor_sync(0xffffffffu, pm1, 1);
        pm1 += __shfl_xor_sync(0xffffffffu, pm1, 2);
        se0 = se0 * c0 + pe0; se1 = se1 * c1 + pe1;
        sq0 = sq0 * c0 + pm0; sq1 = sq1 * c1 + pm1;
        #pragma unroll
        for (int nt = 0; nt < 8; nt++) {
            acc[nt][0] *= c0; acc[nt][1] *= c0;
            acc[nt][2] *= c1; acc[nt][3] *= c1;
        }

        // acc += P @ V : m16 x n64(dh), k = 64 keys, P from registers
        #pragma unroll
        for (int ks = 0; ks < 4; ks++) {
            uint32_t a[4];
            a[0] = p0[2 * ks];     a[1] = p1[2 * ks];
            a[2] = p0[2 * ks + 1]; a[3] = p1[2 * ks + 1];
            const int kk = ks * 16 + 2 * tg;
            #pragma unroll
            for (int nt = 0; nt < 8; nt++) {
                uint32_t b[2];
                b[0] = *(const uint32_t*)&Vs[(nt * 8 + g) * 72 + kk];
                b[1] = *(const uint32_t*)&Vs[(nt * 8 + g) * 72 + kk + 8];
                mma16(acc[nt], a, b);
            }
        }
    }

    // epilogue: renorm, write z fp16 [token][h*64+d]
    float inv0 = 1.0f / (sq0 + 1e-10f * se0 + 1e-30f);
    float inv1 = 1.0f / (sq1 + 1e-10f * se1 + 1e-30f);
    #pragma unroll
    for (int nt = 0; nt < 8; nt++) {
        int c = hc + nt * 8 + 2 * tg;
        *(uint32_t*)&z[(tok0 + m0 + g) * D_ + c] =
            h2pack(acc[nt][0] * inv0, acc[nt][1] * inv0);
        *(uint32_t*)&z[(tok0 + m0 + g + 8) * D_ + c] =
            h2pack(acc[nt][2] * inv1, acc[nt][3] * inv1);
    }
}

// ---------------------------------------------------------------------------
extern "C" void kernel_launch(void* const* d_in, const int* in_sizes, int n_in,
                              void* d_out, int out_size)
{
    const float* x    = (const float*)d_in[0];
    const float* mask = (const float*)d_in[1];
    const float* Wqkv = (const float*)d_in[2];
    const float* Wout = (const float*)d_in[3];
    const float* bout = (const float*)d_in[4];
    float* out = (float*)d_out;

    __half *qkvh, *vt, *zh, *xh, *wqt, *wot;
    cudaGetSymbolAddress((void**)&qkvh, g_qkvh);
    cudaGetSymbolAddress((void**)&vt,   g_vt);
    cudaGetSymbolAddress((void**)&zh,   g_zh);
    cudaGetSymbolAddress((void**)&xh,   g_xh);
    cudaGetSymbolAddress((void**)&wqt,  g_wqt);
    cudaGetSymbolAddress((void**)&wot,  g_wot);

    cudaFuncSetAttribute(hgemm<true>,
                         cudaFuncAttributeMaxDynamicSharedMemorySize, HGEMM_SMEM);
    cudaFuncSetAttribute(hgemm<false>,
                         cudaFuncAttributeMaxDynamicSharedMemorySize, HGEMM_SMEM);
    cudaFuncSetAttribute(attn_mma,
                         cudaFuncAttributeMaxDynamicSharedMemorySize, ATTN_SMEM);

    // 0) operand prep: x -> fp16; W -> transposed fp16 (k-contiguous B tiles)
    f32_to_f16<<<MT_ * D_ / (256 * 8), 256>>>(x, xh);
    transpose_pack<<<dim3(N3_ / 64, D_ / 64), 256>>>(Wqkv, wqt, D_, N3_);
    transpose_pack<<<dim3(D_ / 64, D_ / 64), 256>>>(Wout, wot, D_, D_);

    // 1) QKV projection (fp16 mma; Q columns pre-scaled by 0.125)
    hgemm<true><<<dim3(N3_ / 128, MT_ / 128), 256, HGEMM_SMEM>>>(
        xh, wqt, nullptr, qkvh, MT_, N3_, D_);

    // 1b) V transposed per (b,h) for the PV mma
    v_transpose<<<dim3(32, L_ / 64), 256>>>(qkvh, vt);

    // 2) masked flash attention (fp16 mma, fp32 softmax; writes fp16 z)
    attn_mma<<<dim3(L_ / 128, B_ * H_), 256, ATTN_SMEM>>>(qkvh, vt, mask, zh);

    // 3) output projection + bias (fp16 mma, fp32 output)
    hgemm<false><<<dim3(D_ / 128, MT_ / 128), 256, HGEMM_SMEM>>>(
        zh, wot, bout, out, MT_, D_, D_);
}

// round 16
// speedup vs baseline: 3.1714x; 1.0094x over previous
#include <cuda_runtime.h>
#include <cuda_fp16.h>
#include <stdint.h>

#define B_   2
#define L_   2048
#define D_   1024
#define H_   16
#define N3_  3072
#define MT_  4096

// scratch (allocation-free rule: device globals); 16B+ aligned for uint4/cp.async
__device__ __align__(256) __half g_qkvh[(size_t)MT_ * N3_];   // fp16 qkv (Q pre-scaled)
__device__ __align__(256) __half g_vt[(size_t)32 * 64 * L_];  // V^T fp16
__device__ __align__(256) __half g_zh[(size_t)MT_ * D_];      // fp16 attn out
__device__ __align__(256) __half g_xh[(size_t)MT_ * D_];      // fp16 x
__device__ __align__(256) __half g_wqt[(size_t)N3_ * D_];     // W_qkv^T fp16
__device__ __align__(256) __half g_wot[(size_t)D_ * D_];      // W_out^T fp16

// pack (lo, hi) floats -> f16x2 (lo in low half)
__device__ __forceinline__ uint32_t h2pack(float lo, float hi) {
    uint32_t r; asm("cvt.rn.f16x2.f32 %0, %1, %2;" : "=r"(r) : "f"(hi), "f"(lo));
    return r;
}
__device__ __forceinline__ uint32_t hh(__half lo, __half hi) {
    __half2 t = __halves2half2(lo, hi);
    return *(uint32_t*)&t;
}

__device__ __forceinline__ void mma16(float* d, const uint32_t* a, const uint32_t* b) {
    asm volatile(
        "mma.sync.aligned.m16n8k16.row.col.f32.f16.f16.f32 "
        "{%0,%1,%2,%3}, {%4,%5,%6,%7}, {%8,%9}, {%0,%1,%2,%3};\n"
        : "+f"(d[0]), "+f"(d[1]), "+f"(d[2]), "+f"(d[3])
        : "r"(a[0]), "r"(a[1]), "r"(a[2]), "r"(a[3]), "r"(b[0]), "r"(b[1]));
}

// cp.async helpers
__device__ __forceinline__ void cpa(void* s, const void* g) {
    uint32_t sa = (uint32_t)__cvta_generic_to_shared(s);
    asm volatile("cp.async.cg.shared.global [%0], [%1], 16;\n" :: "r"(sa), "l"(g));
}
__device__ __forceinline__ void cpcommit() { asm volatile("cp.async.commit_group;\n"); }
template<int N> __device__ __forceinline__ void cpwait() {
    asm volatile("cp.async.wait_group %0;\n" :: "n"(N));
}

// ---------------------------------------------------------------------------
// fp32 -> fp16 elementwise pack (contiguous buffer, 8 elems/thread)
// ---------------------------------------------------------------------------
__global__ void f32_to_f16(const float* __restrict__ in, __half* __restrict__ out) {
    int i = (blockIdx.x * 256 + threadIdx.x) * 8;
    float4 v0 = *(const float4*)&in[i], v1 = *(const float4*)&in[i + 4];
    uint4 o;
    o.x = h2pack(v0.x, v0.y); o.y = h2pack(v0.z, v0.w);
    o.z = h2pack(v1.x, v1.y); o.w = h2pack(v1.z, v1.w);
    *(uint4*)&out[i] = o;
}

// ---------------------------------------------------------------------------
// Transpose + fp16 pack for BOTH weights in one launch (blockIdx.z selects).
// in fp32 [K][N] -> out fp16 [N][K]. 64x64 tiles. K = D_ for both.
// ---------------------------------------------------------------------------
__global__ void transpose_pack2(const float* __restrict__ in0, __half* __restrict__ out0,
                                const float* __restrict__ in1, __half* __restrict__ out1) {
    const int zz = blockIdx.z;
    const int N = zz ? D_ : N3_;
    if (zz && blockIdx.x >= D_ / 64) return;      // Wout grid is narrower
    const float* in  = zz ? in1 : in0;
    __half*      out = zz ? out1 : out0;
    const int K = D_;

    __shared__ float ts[64][68];
    const int n0 = blockIdx.x * 64, k0 = blockIdx.y * 64;
    const int tid = threadIdx.x;

    int r = tid >> 2, c0 = (tid & 3) * 16;        // ts[k][n]
    #pragma unroll
    for (int j = 0; j < 4; j++) {
        float4 v = *(const float4*)&in[(size_t)(k0 + r) * N + n0 + c0 + 4 * j];
        *(float4*)&ts[r][c0 + 4 * j] = v;
    }
    __syncthreads();

    int n = tid & 63, kk = (tid >> 6) * 16;       // 16 k per thread
    uint4 o0, o1;
    o0.x = h2pack(ts[kk +  0][n], ts[kk +  1][n]);
    o0.y = h2pack(ts[kk +  2][n], ts[kk +  3][n]);
    o0.z = h2pack(ts[kk +  4][n], ts[kk +  5][n]);
    o0.w = h2pack(ts[kk +  6][n], ts[kk +  7][n]);
    o1.x = h2pack(ts[kk +  8][n], ts[kk +  9][n]);
    o1.y = h2pack(ts[kk + 10][n], ts[kk + 11][n]);
    o1.z = h2pack(ts[kk + 12][n], ts[kk + 13][n]);
    o1.w = h2pack(ts[kk + 14][n], ts[kk + 15][n]);
    size_t orow = (size_t)(n0 + n) * K + k0 + kk;
    *(uint4*)&out[orow]     = o0;
    *(uint4*)&out[orow + 8] = o1;
}

// ---------------------------------------------------------------------------
// V transpose: qkvh V-part fp16 [token][dh] -> vt[bh][dh][token] fp16
// ---------------------------------------------------------------------------
__global__ void v_transpose(const __half* __restrict__ qkvh, __half* __restrict__ vt) {
    __shared__ __half ts[64][72];
    const int bh = blockIdx.x;             // b*16 + h
    const int t0 = blockIdx.y * 64;
    const int b = bh >> 4, hc = (bh & 15) * 64;
    const int tid = threadIdx.x;

    #pragma unroll
    for (int i = 0; i < 2; i++) {
        int id = tid + 256 * i;                  // 0..511 chunks of 8 halves
        int row = id >> 3, c = (id & 7) * 8;
        *(uint4*)&ts[row][c] =
            *(const uint4*)&qkvh[(size_t)(b * L_ + t0 + row) * N3_ + 2048 + hc + c];
    }
    __syncthreads();

    int dh = tid & 63, k0 = (tid >> 6) * 16;     // 16 tokens per thread
    uint4 o0, o1;
    o0.x = hh(ts[k0 +  0][dh], ts[k0 +  1][dh]);
    o0.y = hh(ts[k0 +  2][dh], ts[k0 +  3][dh]);
    o0.z = hh(ts[k0 +  4][dh], ts[k0 +  5][dh]);
    o0.w = hh(ts[k0 +  6][dh], ts[k0 +  7][dh]);
    o1.x = hh(ts[k0 +  8][dh], ts[k0 +  9][dh]);
    o1.y = hh(ts[k0 + 10][dh], ts[k0 + 11][dh]);
    o1.z = hh(ts[k0 + 12][dh], ts[k0 + 13][dh]);
    o1.w = hh(ts[k0 + 14][dh], ts[k0 + 15][dh]);
    size_t vrow = ((size_t)bh * 64 + dh) * L_ + t0 + k0;
    *(uint4*)&vt[vrow]     = o0;
    *(uint4*)&vt[vrow + 8] = o1;
}

// ---------------------------------------------------------------------------
// fp16 mma GEMM: C[M,N] = A[M,K] @ Bt[N,K]^T, fp32 accum.
// 128x128 tile, K-chunk 64, 3-stage cp.async ring -> ONE barrier/iteration
// (buffer (it+2)%3 was last read at iter it-1; top barrier fences its reuse).
// smem 3 x 36864 = 110592 B; 2 CTAs/SM = 224 KB (post-rounding) <= 228 KB.
// smem stride 72 halves: frag bank = (36g+tg)%32 — bijective, conflict-free.
// OUTF16: fp16 out, Q columns (<D_) pre-scaled by 0.125. else: +bias fp32.
// ---------------------------------------------------------------------------
#define HKC 64
#define H_ST 72
#define HSTG (256 * H_ST)                 // halves per stage (A128 + B128 rows)
#define HGEMM_SMEM (3 * HSTG * 2)         // 110592 bytes

template<bool OUTF16>
__global__ __launch_bounds__(256, 2)
void hgemm(const __half* __restrict__ A, const __half* __restrict__ Bt,
           const float* __restrict__ bias, void* __restrict__ Cout,
           int M, int N, int K)
{
    extern __shared__ __half hsm[];
    const int tid  = threadIdx.x;
    const int w    = tid >> 5, lane = tid & 31;
    const int g    = lane >> 2, tg = lane & 3;
    const int wm   = (w >> 2) * 64;
    const int wn   = (w & 3) * 32;
    const int row0 = blockIdx.y * 128, col0 = blockIdx.x * 128;

    float acc[16][4];
    #pragma unroll
    for (int i = 0; i < 16; i++)
        #pragma unroll
        for (int j = 0; j < 4; j++) acc[i][j] = 0.f;

    const int nIter = K / HKC;

    auto load_stage = [&](int it, int buf) {
        const int k0 = it * HKC;
        __half* as = hsm + buf * HSTG;
        __half* bs = as + 128 * H_ST;
        #pragma unroll
        for (int i = 0; i < 4; i++) {
            int id = tid + 256 * i;               // 1024 chunks of 8 halves
            int r = id >> 3, c = (id & 7) * 8;    // 128 rows x 64 halves
            cpa(&as[r * H_ST + c], &A[(size_t)(row0 + r) * K + k0 + c]);
            cpa(&bs[r * H_ST + c], &Bt[(size_t)(col0 + r) * K + k0 + c]);
        }
    };

    load_stage(0, 0); cpcommit();
    load_stage(1, 1); cpcommit();

    int cur = 0, nx2 = 2;
    for (int it = 0; it < nIter; it++) {
        cpwait<1>();                      // group it arrived
        __syncthreads();                  // all warps done with buffer nx2 (iter it-1)
        if (it + 2 < nIter) load_stage(it + 2, nx2);
        cpcommit();

        const __half* as = hsm + cur * HSTG;
        const __half* bs = as + 128 * H_ST;
        #pragma unroll
        for (int ks = 0; ks < 4; ks++) {
            const int kk = ks * 16 + 2 * tg;
            uint32_t a[4][4], b[4][2];
            #pragma unroll
            for (int mt = 0; mt < 4; mt++) {
                const int m = wm + mt * 16;
                a[mt][0] = *(const uint32_t*)&as[(m + g    ) * H_ST + kk];
                a[mt][1] = *(const uint32_t*)&as[(m + g + 8) * H_ST + kk];
                a[mt][2] = *(const uint32_t*)&as[(m + g    ) * H_ST + kk + 8];
                a[mt][3] = *(const uint32_t*)&as[(m + g + 8) * H_ST + kk + 8];
            }
            #pragma unroll
            for (int nt = 0; nt < 4; nt++) {
                const int n = wn + nt * 8;
                b[nt][0] = *(const uint32_t*)&bs[(n + g) * H_ST + kk];
                b[nt][1] = *(const uint32_t*)&bs[(n + g) * H_ST + kk + 8];
            }
            #pragma unroll
            for (int mt = 0; mt < 4; mt++)
                #pragma unroll
                for (int nt = 0; nt < 4; nt++)
                    mma16(acc[mt * 4 + nt], a[mt], b[nt]);
        }
        cur = (cur == 2) ? 0 : cur + 1;
        nx2 = (nx2 == 2) ? 0 : nx2 + 1;
    }

    #pragma unroll
    for (int mt = 0; mt < 4; mt++) {
        #pragma unroll
        for (int nt = 0; nt < 4; nt++) {
            int r = row0 + wm + mt * 16 + g;
            int c = col0 + wn + nt * 8 + 2 * tg;
            float v0 = acc[mt * 4 + nt][0], v1 = acc[mt * 4 + nt][1];
            float v2 = acc[mt * 4 + nt][2], v3 = acc[mt * 4 + nt][3];
            if (OUTF16) {
                // Q columns pre-scaled by softmax 1/sqrt(dh) = 0.125 (exact)
                float sc = (c < D_) ? 0.125f : 1.0f;
                __half* C = (__half*)Cout;
                *(uint32_t*)&C[(size_t)r * N + c]       = h2pack(v0 * sc, v1 * sc);
                *(uint32_t*)&C[(size_t)(r + 8) * N + c] = h2pack(v2 * sc, v3 * sc);
            } else {
                float* C = (float*)Cout;
                float b0 = bias[c], b1 = bias[c + 1];
                *(float2*)&C[(size_t)r * N + c]       = make_float2(v0 + b0, v1 + b1);
                *(float2*)&C[(size_t)(r + 8) * N + c] = make_float2(v2 + b0, v3 + b1);
            }
        }
    }
}

// ---------------------------------------------------------------------------
// Flash attention (R15, measured): fp16 mma, fp32 softmax (MUFU exp),
// 3-buffer K/V ring, ONE barrier/iter, mask prefetched to registers,
// Q pre-scaled by 0.125 upstream.
//   out = sum(e^{s-m}*mask*v) / (sum(e^{s-m}*mask) + eps*sum(e^{s-m}))
// ---------------------------------------------------------------------------
#define QS_B 0                            // Qs: 128*72*2 = 18432 B
#define KS_B 18432                        // Ks: 3 x 64*72*2 = 27648 B
#define VT_B (18432 + 27648)              // Vt: 3 x 64*72*2
#define ATTN_SMEM (VT_B + 27648)          // 73728 B total

__global__ __launch_bounds__(256, 2)
void attn_mma(const __half* __restrict__ qkvh,
              const __half* __restrict__ vtg,
              const float* __restrict__ mask, __half* __restrict__ z)
{
    extern __shared__ char smc[];
    __half* Qs = (__half*)(smc + QS_B);

    const int tid = threadIdx.x;
    const int w = tid >> 5, lane = tid & 31;
    const int g = lane >> 2, tg = lane & 3;
    const int m0 = w * 16;
    const int bb = blockIdx.y >> 4;
    const int h  = blockIdx.y & 15;
    const int qi0 = blockIdx.x * 128;
    const size_t tok0 = (size_t)bb * L_ + qi0;
    const int hc = h * 64;

    auto load_kv = [&](int kt) {
        __half* ks = (__half*)(smc + KS_B + (kt % 3) * 9216);
        __half* vs = (__half*)(smc + VT_B + (kt % 3) * 9216);
        int r = tid >> 2, c0 = (tid & 3) * 16;
        const size_t ktok = (size_t)bb * L_ + kt * 64;
        cpa(&ks[r * 72 + c0],     &qkvh[(ktok + r) * N3_ + 1024 + hc + c0]);
        cpa(&ks[r * 72 + c0 + 8], &qkvh[(ktok + r) * N3_ + 1024 + hc + c0 + 8]);
        const size_t vrow = ((size_t)(bb * 16 + h) * 64 + r) * L_ + kt * 64;
        cpa(&vs[r * 72 + c0],     &vtg[vrow + c0]);
        cpa(&vs[r * 72 + c0 + 8], &vtg[vrow + c0 + 8]);
    };

    // prologue: group0 = Q + K/V(0); group1 = K/V(1)
    {
        int r = tid >> 1, c0 = (tid & 1) * 32;
        #pragma unroll
        for (int j = 0; j < 4; j++)
            cpa(&Qs[r * 72 + c0 + 8 * j], &qkvh[(tok0 + r) * N3_ + hc + c0 + 8 * j]);
    }
    load_kv(0); cpcommit();
    load_kv(1); cpcommit();

    float acc[8][4];
    #pragma unroll
    for (int i = 0; i < 8; i++)
        #pragma unroll
        for (int j = 0; j < 4; j++) acc[i][j] = 0.f;
    float mp0 = -1e30f, mp1 = -1e30f;
    float se0 = 0.f, se1 = 0.f, sq0 = 0.f, sq1 = 0.f;

    const float* mrow0 = mask + (tok0 + m0 + g) * L_ + 2 * tg;
    const float* mrow1 = mrow0 + 8 * (size_t)L_;
    const int qrow0 = (m0 + g) * 72, qrow1 = (m0 + g + 8) * 72;

    for (int kt = 0; kt < L_ / 64; kt++) {
        const int kj0 = kt * 64;
        cpwait<1>();                     // group kt complete
        __syncthreads();                 // all warps done with buffer (kt+2)%3
        if (kt + 2 < L_ / 64) load_kv(kt + 2);
        cpcommit();

        // prefetch mask tile into registers — consumed AFTER the S-mma
        float2 mk0[8], mk1[8];
        #pragma unroll
        for (int nt = 0; nt < 8; nt++) {
            mk0[nt] = *(const float2*)&mrow0[kj0 + nt * 8];
            mk1[nt] = *(const float2*)&mrow1[kj0 + nt * 8];
        }

        const __half* Ks = (const __half*)(smc + KS_B + (kt % 3) * 9216);
        const __half* Vs = (const __half*)(smc + VT_B + (kt % 3) * 9216);

        // S = (Q/8) @ K^T : m16 x n64, fp16 k16 x 4 steps
        float s[8][4];
        #pragma unroll
        for (int nt = 0; nt < 8; nt++)
            #pragma unroll
            for (int j = 0; j < 4; j++) s[nt][j] = 0.f;
        #pragma unroll
        for (int ks = 0; ks < 4; ks++) {
            const int kk = ks * 16 + 2 * tg;
            uint32_t a[4];
            a[0] = *(const uint32_t*)&Qs[qrow0 + kk];
            a[1] = *(const uint32_t*)&Qs[qrow1 + kk];
            a[2] = *(const uint32_t*)&Qs[qrow0 + kk + 8];
            a[3] = *(const uint32_t*)&Qs[qrow1 + kk + 8];
            #pragma unroll
            for (int nt = 0; nt < 8; nt++) {
                uint32_t b[2];
                b[0] = *(const uint32_t*)&Ks[(nt * 8 + g) * 72 + kk];
                b[1] = *(const uint32_t*)&Ks[(nt * 8 + g) * 72 + kk + 8];
                mma16(s[nt], a, b);
            }
        }

        // warp-local online softmax (rows g and g+8; scores pre-scaled)
        float r0 = -1e30f, r1 = -1e30f;
        #pragma unroll
        for (int nt = 0; nt < 8; nt++) {
            r0 = fmaxf(r0, fmaxf(s[nt][0], s[nt][1]));
            r1 = fmaxf(r1, fmaxf(s[nt][2], s[nt][3]));
        }
        r0 = fmaxf(r0, __shfl_xor_sync(0xffffffffu, r0, 1));
        r0 = fmaxf(r0, __shfl_xor_sync(0xffffffffu, r0, 2));
        r1 = fmaxf(r1, __shfl_xor_sync(0xffffffffu, r1, 1));
        r1 = fmaxf(r1, __shfl_xor_sync(0xffffffffu, r1, 2));

        float mn0 = fmaxf(mp0, r0), mn1 = fmaxf(mp1, r1);
        float c0 = __expf(mp0 - mn0), c1 = __expf(mp1 - mn1);
        mp0 = mn0; mp1 = mn1;

        uint32_t p0[8], p1[8];     // masked P, f16x2, rows g / g+8
        float pe0 = 0.f, pe1 = 0.f, pm0 = 0.f, pm1 = 0.f;
        #pragma unroll
        for (int nt = 0; nt < 8; nt++) {
            float p00 = __expf(s[nt][0] - mn0);
            float p01 = __expf(s[nt][1] - mn0);
            float p10 = __expf(s[nt][2] - mn1);
            float p11 = __expf(s[nt][3] - mn1);
            pe0 += p00 + p01; pe1 += p10 + p11;
            float q00 = p00 * mk0[nt].x, q01 = p01 * mk0[nt].y;
            float q10 = p10 * mk1[nt].x, q11 = p11 * mk1[nt].y;
            pm0 += q00 + q01; pm1 += q10 + q11;
            p0[nt] = h2pack(q00, q01);
            p1[nt] = h2pack(q10, q11);
        }
        pe0 += __shfl_xor_sync(0xffffffffu, pe0, 1);
        pe0 += __shfl_xor_sync(0xffffffffu, pe0, 2);
        pe1 += __shfl_xor_sync(0xffffffffu, pe1, 1);
        pe1 += __shfl_xor_sync(0xffffffffu, pe1, 2);
        pm0 += __shfl_xor_sync(0xffffffffu, pm0, 1);
        pm0 += __shfl_xor_sync(0xffffffffu, pm0, 2);
        pm1 += __shfl_xor_sync(0xffffffffu, pm1, 1);
        pm1 += __shfl_xor_sync(0xffffffffu, pm1, 2);
        se0 = se0 * c0 + pe0; se1 = se1 * c1 + pe1;
        sq0 = sq0 * c0 + pm0; sq1 = sq1 * c1 + pm1;
        #pragma unroll
        for (int nt = 0; nt < 8; nt++) {
            acc[nt][0] *= c0; acc[nt][1] *= c0;
            acc[nt][2] *= c1; acc[nt][3] *= c1;
        }

        // acc += P @ V : m16 x n64(dh), k = 64 keys, P from registers
        #pragma unroll
        for (int ks = 0; ks < 4; ks++) {
            uint32_t a[4];
            a[0] = p0[2 * ks];     a[1] = p1[2 * ks];
            a[2] = p0[2 * ks + 1]; a[3] = p1[2 * ks + 1];
            const int kk = ks * 16 + 2 * tg;
            #pragma unroll
            for (int nt = 0; nt < 8; nt++) {
                uint32_t b[2];
                b[0] = *(const uint32_t*)&Vs[(nt * 8 + g) * 72 + kk];
                b[1] = *(const uint32_t*)&Vs[(nt * 8 + g) * 72 + kk + 8];
                mma16(acc[nt], a, b);
            }
        }
    }

    // epilogue: renorm, write z fp16 [token][h*64+d]
    float inv0 = 1.0f / (sq0 + 1e-10f * se0 + 1e-30f);
    float inv1 = 1.0f / (sq1 + 1e-10f * se1 + 1e-30f);
    #pragma unroll
    for (int nt = 0; nt < 8; nt++) {
        int c = hc + nt * 8 + 2 * tg;
        *(uint32_t*)&z[(tok0 + m0 + g) * D_ + c] =
            h2pack(acc[nt][0] * inv0, acc[nt][1] * inv0);
        *(uint32_t*)&z[(tok0 + m0 + g + 8) * D_ + c] =
            h2pack(acc[nt][2] * inv1, acc[nt][3] * inv1);
    }
}

// ---------------------------------------------------------------------------
extern "C" void kernel_launch(void* const* d_in, const int* in_sizes, int n_in,
                              void* d_out, int out_size)
{
    const float* x    = (const float*)d_in[0];
    const float* mask = (const float*)d_in[1];
    const float* Wqkv = (const float*)d_in[2];
    const float* Wout = (const float*)d_in[3];
    const float* bout = (const float*)d_in[4];
    float* out = (float*)d_out;

    __half *qkvh, *vt, *zh, *xh, *wqt, *wot;
    cudaGetSymbolAddress((void**)&qkvh, g_qkvh);
    cudaGetSymbolAddress((void**)&vt,   g_vt);
    cudaGetSymbolAddress((void**)&zh,   g_zh);
    cudaGetSymbolAddress((void**)&xh,   g_xh);
    cudaGetSymbolAddress((void**)&wqt,  g_wqt);
    cudaGetSymbolAddress((void**)&wot,  g_wot);

    cudaFuncSetAttribute(hgemm<true>,
                         cudaFuncAttributeMaxDynamicSharedMemorySize, HGEMM_SMEM);
    cudaFuncSetAttribute(hgemm<false>,
                         cudaFuncAttributeMaxDynamicSharedMemorySize, HGEMM_SMEM);
    cudaFuncSetAttribute(attn_mma,
                         cudaFuncAttributeMaxDynamicSharedMemorySize, ATTN_SMEM);

    // 0) operand prep: x -> fp16; both W -> transposed fp16, one launch
    f32_to_f16<<<MT_ * D_ / (256 * 8), 256>>>(x, xh);
    transpose_pack2<<<dim3(N3_ / 64, D_ / 64, 2), 256>>>(Wqkv, wqt, Wout, wot);

    // 1) QKV projection (fp16 mma; Q columns pre-scaled by 0.125)
    hgemm<true><<<dim3(N3_ / 128, MT_ / 128), 256, HGEMM_SMEM>>>(
        xh, wqt, nullptr, qkvh, MT_, N3_, D_);

    // 1b) V transposed per (b,h) for the PV mma
    v_transpose<<<dim3(32, L_ / 64), 256>>>(qkvh, vt);

    // 2) masked flash attention (fp16 mma, fp32 softmax; writes fp16 z)
    attn_mma<<<dim3(L_ / 128, B_ * H_), 256, ATTN_SMEM>>>(qkvh, vt, mask, zh);

    // 3) output projection + bias (fp16 mma, fp32 output)
    hgemm<false><<<dim3(D_ / 128, MT_ / 128), 256, HGEMM_SMEM>>>(
        zh, wot, bout, out, MT_, D_, D_);
}